// round 7
// baseline (speedup 1.0000x reference)
#include <cuda_runtime.h>

#define NTOK  49
#define SCALE 0.17677669529663687f
#define NTHR  512

// u2 (8-byte) offsets
#define O_X   0        // R1: x -> q packed, 112 x 68 = 7616
#define O_W   7616     // R2: weight chunk 64 x 68 (region 4992 incl. attn spill)
#define O_K   12608    // R3: k packed 112 x 68 = 7616 ; later OV
#define O_VT  20224    // R4: vT packed [2][128][34] = 8704
#define SM_U2 28928    // 231,424 bytes
#define VSTR  34
// attn overlay: [0, 12544) over R1+R2 : [(win*4+h)*49+i]*32 + u

__device__ uint2 gW[8 * 64 * 64];   // pre-split weights, 8 chunks of 64 cols

__device__ __forceinline__ unsigned pack_bf(float x0, float x1) {
    unsigned r;
    asm("cvt.rn.bf16x2.f32 %0, %1, %2;" : "=r"(r) : "f"(x1), "f"(x0));
    return r;
}
__device__ __forceinline__ uint2 split_pack(float x0, float x1) {
    unsigned h = pack_bf(x0, x1);
    float h0 = __uint_as_float(h << 16);
    float h1 = __uint_as_float(h & 0xffff0000u);
    unsigned l = pack_bf(x0 - h0, x1 - h1);
    return make_uint2(h, l);
}
__device__ __forceinline__ void mmabf(float* d, const unsigned* a, const unsigned* b) {
    asm volatile("mma.sync.aligned.m16n8k16.row.col.f32.bf16.bf16.f32 "
        "{%0,%1,%2,%3},{%4,%5,%6,%7},{%8,%9},{%0,%1,%2,%3};"
        : "+f"(d[0]), "+f"(d[1]), "+f"(d[2]), "+f"(d[3])
        : "r"(a[0]), "r"(a[1]), "r"(a[2]), "r"(a[3]), "r"(b[0]), "r"(b[1]));
}
__device__ __forceinline__ void mma3(float* d, const unsigned ah[4], const unsigned al[4],
                                     uint2 b0, uint2 b1) {
    unsigned bh[2] = {b0.x, b1.x};
    unsigned bl[2] = {b0.y, b1.y};
    mmabf(d, ah, bl);
    mmabf(d, al, bh);
    mmabf(d, ah, bh);
}

// D(16x32 per warp) = A(rows ra/ra8.., K=128) x W^T(cols wc+8nb), all pre-split
__device__ __forceinline__ void mma_dense(const uint2* __restrict__ A,
                                          const uint2* __restrict__ W,
                                          float d[4][4], int ra, int ra8, int wc, int t)
{
    #pragma unroll
    for (int kb = 0; kb < 8; ++kb) {
        const int kw = kb * 8 + t;
        uint2 a0 = A[ra  * 68 + kw];
        uint2 a1 = A[ra8 * 68 + kw];
        uint2 a2 = A[ra  * 68 + kw + 4];
        uint2 a3 = A[ra8 * 68 + kw + 4];
        unsigned ah[4] = {a0.x, a1.x, a2.x, a3.x};
        unsigned al[4] = {a0.y, a1.y, a2.y, a3.y};
        #pragma unroll
        for (int nb = 0; nb < 4; ++nb)
            mma3(d[nb], ah, al, W[(wc + nb * 8) * 68 + kw],
                                W[(wc + nb * 8) * 68 + kw + 4]);
    }
}

__global__ void prep_kernel(const float* __restrict__ qkv_w,
                            const float* __restrict__ proj_w)
{
    int idx = blockIdx.x * blockDim.x + threadIdx.x;   // 0..32767
    int c = idx >> 6, u = idx & 63;
    const float* src = (c < 384) ? (qkv_w + (size_t)c * 128)
                                 : (proj_w + (size_t)(c - 384) * 128);
    gW[idx] = split_pack(src[2 * u], src[2 * u + 1]);
}

__global__ __launch_bounds__(NTHR, 1)
void wmsa_fused_kernel(const float* __restrict__ x,
                       const float* __restrict__ attn_mask,
                       const float* __restrict__ qkv_b,
                       const float* __restrict__ proj_b,
                       const float* __restrict__ bias_table,
                       const int*   __restrict__ rel_idx,
                       float* __restrict__ out)
{
    extern __shared__ uint2 smu[];
    uint2* XH = smu + O_X;     // x then q
    uint2* WH = smu + O_W;
    uint2* KH = smu + O_K;
    uint2* VT = smu + O_VT;
    uint2* AT = smu;           // attn overlay (R1+R2)
    uint2* OV = smu + O_K;     // overlay KH

    const int tid  = threadIdx.x;
    const int bx   = blockIdx.x;
    const int lane = tid & 31;
    const int wid  = tid >> 5;
    const int g    = lane >> 2;
    const int t    = lane & 3;

    // dense-GEMM roles: 8 m-tiles x 2 n-halves
    const int mt = wid >> 1, nh = wid & 1;
    const int r0 = mt * 16 + g, r1 = r0 + 8;
    const int ra = min(r0, 111), ra8 = min(r1, 111);
    const bool act = (mt < 7);
    const int win0 = (r0 >= 56), win1 = (r1 >= 56);
    const int i0 = r0 - 56 * win0, i1 = r1 - 56 * win1;
    const bool v0ok = act && (i0 < 49);
    const bool v1ok = act && (i1 < 49);
    const int wc = nh * 32 + g;

    // ---------------- phase 0: load+split x (2 windows); zero KH pads + VT ----------------
    for (int idx = tid; idx < 2 * 49 * 64; idx += NTHR) {
        int wloc = idx / 3136, rem = idx - wloc * 3136;
        int i = rem >> 6, u = rem & 63;
        const float* xg = x + ((size_t)(2 * bx + wloc) * 49 + i) * 128;
        float2 v = *(const float2*)(xg + 2 * u);
        XH[(wloc * 56 + i) * 68 + u] = split_pack(v.x, v.y);
    }
    for (int idx = tid; idx < 14 * 68; idx += NTHR) {
        int r = idx / 68, c = idx - r * 68;
        int row = (r < 7) ? (49 + r) : (98 + r);      // rows 49..55, 105..111
        KH[row * 68 + c] = make_uint2(0, 0);
    }
    for (int idx = tid; idx < 2 * 128 * VSTR; idx += NTHR)
        VT[idx] = make_uint2(0, 0);

    // ---------------- phase 1a: K and V chunks ----------------
    #pragma unroll 1
    for (int s = 0; s < 4; ++s) {
        const int ci = s + 2;                          // chunks 2,3 = k ; 4,5 = v
        __syncthreads();
        const uint2* gsrc = gW + (size_t)ci * 4096;
        for (int idx = tid; idx < 4096; idx += NTHR)
            WH[(idx >> 6) * 68 + (idx & 63)] = gsrc[idx];
        __syncthreads();
        if (!act) continue;

        float d[4][4] = {};
        mma_dense(XH, WH, d, ra, ra8, wc, t);

        if (s < 2) {
            #pragma unroll
            for (int nb = 0; nb < 4; ++nb) {
                int lc = nh * 32 + nb * 8 + 2 * t;
                int gc = (ci - 2) * 64 + lc;
                float b0 = qkv_b[128 + gc], b1 = qkv_b[129 + gc];
                int wcol = gc >> 1;
                if (v0ok) KH[r0 * 68 + wcol] = split_pack(d[nb][0] + b0, d[nb][1] + b1);
                if (v1ok) KH[r1 * 68 + wcol] = split_pack(d[nb][2] + b0, d[nb][3] + b1);
            }
        } else {
            // V: pair tokens via shfl (lane^4 flips g parity), store u2 into VT
            #pragma unroll
            for (int nb = 0; nb < 4; ++nb) {
                int lc = nh * 32 + nb * 8 + 2 * t;
                int c = (ci - 4) * 64 + lc;
                float b0 = qkv_b[256 + c], b1 = qkv_b[257 + c];
                #pragma unroll
                for (int rr = 0; rr < 2; ++rr) {
                    float vc  = d[nb][2 * rr]     + b0;
                    float vc1 = d[nb][2 * rr + 1] + b1;
                    float oc  = __shfl_xor_sync(0xffffffffu, vc, 4);
                    float oc1 = __shfl_xor_sync(0xffffffffu, vc1, 4);
                    int row = rr ? r1 : r0;
                    int wn = (row >= 56), il = row - 56 * wn;
                    if (!(g & 1) && il < 49) {
                        float e1 = (il + 1 < 49) ? oc  : 0.f;
                        float f1 = (il + 1 < 49) ? oc1 : 0.f;
                        int u = il >> 1;
                        VT[(wn * 128 + c)     * VSTR + u] = split_pack(vc,  e1);
                        VT[(wn * 128 + c + 1) * VSTR + u] = split_pack(vc1, f1);
                    }
                }
            }
        }
    }

    // ---------------- phase 1b: Q chunks (regs), then overwrite XH with q ----------------
    float dq0[4][4] = {}, dq1[4][4] = {};
    __syncthreads();
    for (int idx = tid; idx < 4096; idx += NTHR)
        WH[(idx >> 6) * 68 + (idx & 63)] = gW[idx];
    __syncthreads();
    if (act) mma_dense(XH, WH, dq0, ra, ra8, wc, t);
    __syncthreads();
    for (int idx = tid; idx < 4096; idx += NTHR)
        WH[(idx >> 6) * 68 + (idx & 63)] = gW[4096 + idx];
    __syncthreads();
    if (act) mma_dense(XH, WH, dq1, ra, ra8, wc, t);
    __syncthreads();                                   // all q-mma reads of XH done
    if (act) {
        #pragma unroll
        for (int nb = 0; nb < 4; ++nb) {
            int lc = nh * 32 + nb * 8 + 2 * t;
            {
                int gc = lc;
                float b0 = qkv_b[gc], b1 = qkv_b[gc + 1];
                int wcol = gc >> 1;
                if (v0ok) XH[r0 * 68 + wcol] =
                    split_pack((dq0[nb][0] + b0) * SCALE, (dq0[nb][1] + b1) * SCALE);
                if (v1ok) XH[r1 * 68 + wcol] =
                    split_pack((dq0[nb][2] + b0) * SCALE, (dq0[nb][3] + b1) * SCALE);
            }
            {
                int gc = 64 + lc;
                float b0 = qkv_b[gc], b1 = qkv_b[gc + 1];
                int wcol = gc >> 1;
                if (v0ok) XH[r0 * 68 + wcol] =
                    split_pack((dq1[nb][0] + b0) * SCALE, (dq1[nb][1] + b1) * SCALE);
                if (v1ok) XH[r1 * 68 + wcol] =
                    split_pack((dq1[nb][2] + b0) * SCALE, (dq1[nb][3] + b1) * SCALE);
            }
        }
    }
    __syncthreads();

    // ---------------- phase 2: QK^T (both tasks into regs) ----------------
    float d2[2][7][4];
    #pragma unroll
    for (int it = 0; it < 2; ++it) {
        int task = wid + 16 * it;
        int qwin = task >> 4, rem = task & 15, h = rem >> 2, qt = rem & 3;
        int l0 = qt * 16 + g;
        int qa0 = qwin * 56 + min(l0, 48);
        int qa1 = qwin * 56 + min(l0 + 8, 48);
        #pragma unroll
        for (int jb = 0; jb < 7; ++jb)
            #pragma unroll
            for (int e = 0; e < 4; ++e) d2[it][jb][e] = 0.f;
        #pragma unroll
        for (int kb = 0; kb < 2; ++kb) {
            int kw = h * 16 + kb * 8 + t;
            uint2 a0 = XH[qa0 * 68 + kw];
            uint2 a1 = XH[qa1 * 68 + kw];
            uint2 a2 = XH[qa0 * 68 + kw + 4];
            uint2 a3 = XH[qa1 * 68 + kw + 4];
            unsigned ah[4] = {a0.x, a1.x, a2.x, a3.x};
            unsigned al[4] = {a0.y, a1.y, a2.y, a3.y};
            #pragma unroll
            for (int jb = 0; jb < 7; ++jb) {
                int kr = qwin * 56 + jb * 8 + g;
                mma3(d2[it][jb], ah, al, KH[kr * 68 + kw], KH[kr * 68 + kw + 4]);
            }
        }
    }
    __syncthreads();    // q/k reads complete; attn region (R1+R2) now writable

    // ---------------- phase 3: bias+mask+softmax in regs, write packed attn ----------------
    #pragma unroll
    for (int it = 0; it < 2; ++it) {
        int task = wid + 16 * it;
        int qwin = task >> 4, rem = task & 15, h = rem >> 2, qt = rem & 3;
        const float* maskg = attn_mask + (size_t)((2 * bx + qwin) & 63) * (NTOK * NTOK);
        #pragma unroll
        for (int rr = 0; rr < 2; ++rr) {
            int li = qt * 16 + g + rr * 8;
            bool okr = (li < 49);
            float sv[14];
            float mx = -INFINITY;
            #pragma unroll
            for (int jb = 0; jb < 7; ++jb) {
                #pragma unroll
                for (int e = 0; e < 2; ++e) {
                    int j = jb * 8 + 2 * t + e;
                    float val = -INFINITY;
                    if (okr && j < 49) {
                        int ij = li * 49 + j;
                        val = d2[it][jb][rr * 2 + e]
                            + bias_table[rel_idx[ij] * 4 + h] + maskg[ij];
                    }
                    sv[jb * 2 + e] = val;
                    mx = fmaxf(mx, val);
                }
            }
            mx = fmaxf(mx, __shfl_xor_sync(0xffffffffu, mx, 1));
            mx = fmaxf(mx, __shfl_xor_sync(0xffffffffu, mx, 2));
            float sum = 0.f;
            #pragma unroll
            for (int n = 0; n < 14; ++n) { sv[n] = __expf(sv[n] - mx); sum += sv[n]; }
            sum += __shfl_xor_sync(0xffffffffu, sum, 1);
            sum += __shfl_xor_sync(0xffffffffu, sum, 2);
            float inv = 1.f / sum;
            if (okr) {
                uint2* arow = AT + ((size_t)(qwin * 4 + h) * 49 + li) * 32;
                #pragma unroll
                for (int jb = 0; jb < 7; ++jb)
                    arow[4 * jb + t] = split_pack(sv[2 * jb] * inv, sv[2 * jb + 1] * inv);
                arow[28 + t] = make_uint2(0, 0);        // zero pad cols 28..31
            }
        }
    }
    __syncthreads();

    // ---------------- phase 4: AV -> OV (overlay KH) ----------------
    #pragma unroll
    for (int it = 0; it < 2; ++it) {
        int task = wid + 16 * it;
        int qwin = task >> 4, rem = task & 15, h = rem >> 2, qt = rem & 3;
        int l0 = qt * 16 + g;
        const uint2* ab = AT + (size_t)(qwin * 4 + h) * 49 * 32;
        int qa0 = min(l0, 48), qa1 = min(l0 + 8, 48);
        float d[4][4] = {};
        #pragma unroll
        for (int kb = 0; kb < 4; ++kb) {
            int kw = kb * 8 + t;
            uint2 a0 = ab[qa0 * 32 + kw];
            uint2 a1 = ab[qa1 * 32 + kw];
            uint2 a2 = ab[qa0 * 32 + kw + 4];
            uint2 a3 = ab[qa1 * 32 + kw + 4];
            unsigned ah[4] = {a0.x, a1.x, a2.x, a3.x};
            unsigned al[4] = {a0.y, a1.y, a2.y, a3.y};
            #pragma unroll
            for (int nb = 0; nb < 4; ++nb) {
                int c = 32 * h + nb * 8 + g;
                mma3(d[nb], ah, al, VT[(qwin * 128 + c) * VSTR + kw],
                                    VT[(qwin * 128 + c) * VSTR + kw + 4]);
            }
        }
        #pragma unroll
        for (int nb = 0; nb < 4; ++nb) {
            int cw = 16 * h + nb * 4 + t;
            if (l0 < 49)
                OV[(qwin * 56 + l0) * 68 + cw] = split_pack(d[nb][0], d[nb][1]);
            if (l0 + 8 < 49)
                OV[(qwin * 56 + l0 + 8) * 68 + cw] = split_pack(d[nb][2], d[nb][3]);
        }
    }

    // ---------------- phase 5: proj GEMM (chunks 6,7) ----------------
    #pragma unroll 1
    for (int s = 0; s < 2; ++s) {
        __syncthreads();
        const uint2* gsrc = gW + (size_t)(6 + s) * 4096;
        for (int idx = tid; idx < 4096; idx += NTHR)
            WH[(idx >> 6) * 68 + (idx & 63)] = gsrc[idx];
        __syncthreads();
        if (!act) continue;

        float d[4][4] = {};
        mma_dense(OV, WH, d, ra, ra8, wc, t);

        #pragma unroll
        for (int nb = 0; nb < 4; ++nb) {
            int lc = nh * 32 + nb * 8 + 2 * t;
            int gc = s * 64 + lc;
            float b0 = proj_b[gc], b1 = proj_b[gc + 1];
            if (v0ok)
                *(float2*)(out + ((size_t)(2 * bx + win0) * 49 + i0) * 128 + gc)
                    = make_float2(d[nb][0] + b0, d[nb][1] + b1);
            if (v1ok)
                *(float2*)(out + ((size_t)(2 * bx + win1) * 49 + i1) * 128 + gc)
                    = make_float2(d[nb][2] + b0, d[nb][3] + b1);
        }
    }
}

extern "C" void kernel_launch(void* const* d_in, const int* in_sizes, int n_in,
                              void* d_out, int out_size)
{
    const float* x          = (const float*)d_in[0];
    const float* attn_mask  = (const float*)d_in[1];
    const float* qkv_w      = (const float*)d_in[2];
    const float* qkv_b      = (const float*)d_in[3];
    const float* proj_w     = (const float*)d_in[4];
    const float* proj_b     = (const float*)d_in[5];
    const float* bias_table = (const float*)d_in[6];
    const int*   rel_idx    = (const int*)d_in[7];
    float* out = (float*)d_out;

    prep_kernel<<<64, 512>>>(qkv_w, proj_w);

    const int smem_bytes = SM_U2 * sizeof(uint2);   // 231,424 B
    cudaFuncSetAttribute(wmsa_fused_kernel,
                         cudaFuncAttributeMaxDynamicSharedMemorySize, smem_bytes);

    const int n_windows = in_sizes[0] / (NTOK * 128);   // 4096
    wmsa_fused_kernel<<<n_windows / 2, NTHR, smem_bytes>>>(
        x, attn_mask, qkv_b, proj_b, bias_table, rel_idx, out);
}

// round 8
// speedup vs baseline: 1.0066x; 1.0066x over previous
#include <cuda_runtime.h>

#define NTOK  49
#define SCALE 0.17677669529663687f
#define NTHR  512

// u2 (8-byte) offsets
#define O_X   0        // R1: x -> q packed, 112 x 68 = 7616
#define O_W   7616     // R2: weight chunk 64 x 68 (region 4992 incl. attn spill)
#define O_K   12608    // R3: k packed 112 x 68 = 7616 ; later OV
#define O_VT  20224    // R4: vT packed [2][128][34] = 8704
#define SM_U2 28928    // 231,424 bytes
#define VSTR  34
// attn overlay: [0, 12544) over R1+R2 : [(win*4+h)*49+i]*32 + u

__device__ uint2 gW[8 * 64 * 64];   // pre-split weights, 8 chunks of 64 cols

__device__ __forceinline__ unsigned pack_bf(float x0, float x1) {
    unsigned r;
    asm("cvt.rn.bf16x2.f32 %0, %1, %2;" : "=r"(r) : "f"(x1), "f"(x0));
    return r;
}
__device__ __forceinline__ uint2 split_pack(float x0, float x1) {
    unsigned h = pack_bf(x0, x1);
    float h0 = __uint_as_float(h << 16);
    float h1 = __uint_as_float(h & 0xffff0000u);
    unsigned l = pack_bf(x0 - h0, x1 - h1);
    return make_uint2(h, l);
}
__device__ __forceinline__ void mmabf(float* d, const unsigned* a, const unsigned* b) {
    asm volatile("mma.sync.aligned.m16n8k16.row.col.f32.bf16.bf16.f32 "
        "{%0,%1,%2,%3},{%4,%5,%6,%7},{%8,%9},{%0,%1,%2,%3};"
        : "+f"(d[0]), "+f"(d[1]), "+f"(d[2]), "+f"(d[3])
        : "r"(a[0]), "r"(a[1]), "r"(a[2]), "r"(a[3]), "r"(b[0]), "r"(b[1]));
}
__device__ __forceinline__ void mma3(float* d, const unsigned ah[4], const unsigned al[4],
                                     uint2 b0, uint2 b1) {
    unsigned bh[2] = {b0.x, b1.x};
    unsigned bl[2] = {b0.y, b1.y};
    mmabf(d, ah, bl);
    mmabf(d, al, bh);
    mmabf(d, ah, bh);
}

// D(16x32 per warp) = A(rows ra/ra8.., K=128) x W^T(cols wc+8nb), all pre-split
__device__ __forceinline__ void mma_dense(const uint2* __restrict__ A,
                                          const uint2* __restrict__ W,
                                          float d[4][4], int ra, int ra8, int wc, int t)
{
    #pragma unroll
    for (int kb = 0; kb < 8; ++kb) {
        const int kw = kb * 8 + t;
        uint2 a0 = A[ra  * 68 + kw];
        uint2 a1 = A[ra8 * 68 + kw];
        uint2 a2 = A[ra  * 68 + kw + 4];
        uint2 a3 = A[ra8 * 68 + kw + 4];
        unsigned ah[4] = {a0.x, a1.x, a2.x, a3.x};
        unsigned al[4] = {a0.y, a1.y, a2.y, a3.y};
        #pragma unroll
        for (int nb = 0; nb < 4; ++nb)
            mma3(d[nb], ah, al, W[(wc + nb * 8) * 68 + kw],
                                W[(wc + nb * 8) * 68 + kw + 4]);
    }
}

__global__ void prep_kernel(const float* __restrict__ qkv_w,
                            const float* __restrict__ proj_w)
{
    int idx = blockIdx.x * blockDim.x + threadIdx.x;   // 0..32767
    int c = idx >> 6, u = idx & 63;
    const float* src = (c < 384) ? (qkv_w + (size_t)c * 128)
                                 : (proj_w + (size_t)(c - 384) * 128);
    gW[idx] = split_pack(src[2 * u], src[2 * u + 1]);
}

__global__ __launch_bounds__(NTHR, 1)
void wmsa_fused_kernel(const float* __restrict__ x,
                       const float* __restrict__ attn_mask,
                       const float* __restrict__ qkv_b,
                       const float* __restrict__ proj_b,
                       const float* __restrict__ bias_table,
                       const int*   __restrict__ rel_idx,
                       float* __restrict__ out)
{
    extern __shared__ uint2 smu[];
    uint2* XH = smu + O_X;     // x then q
    uint2* WH = smu + O_W;
    uint2* KH = smu + O_K;
    uint2* VT = smu + O_VT;
    uint2* AT = smu;           // attn overlay (R1+R2)
    uint2* OV = smu + O_K;     // overlay KH

    const int tid  = threadIdx.x;
    const int bx   = blockIdx.x;
    const int lane = tid & 31;
    const int wid  = tid >> 5;
    const int g    = lane >> 2;
    const int t    = lane & 3;

    // dense-GEMM roles: 8 m-tiles x 2 n-halves
    const int mt = wid >> 1, nh = wid & 1;
    const int r0 = mt * 16 + g, r1 = r0 + 8;
    const int ra = min(r0, 111), ra8 = min(r1, 111);
    const bool act = (mt < 7);
    const int win0 = (r0 >= 56), win1 = (r1 >= 56);
    const int i0 = r0 - 56 * win0, i1 = r1 - 56 * win1;
    const bool v0ok = act && (i0 < 49);
    const bool v1ok = act && (i1 < 49);
    const int wc = nh * 32 + g;

    // ---------------- phase 0: load+split x (2 windows); zero KH pads + VT ----------------
    for (int idx = tid; idx < 2 * 49 * 64; idx += NTHR) {
        int wloc = idx / 3136, rem = idx - wloc * 3136;
        int i = rem >> 6, u = rem & 63;
        const float* xg = x + ((size_t)(2 * bx + wloc) * 49 + i) * 128;
        float2 v = *(const float2*)(xg + 2 * u);
        XH[(wloc * 56 + i) * 68 + u] = split_pack(v.x, v.y);
    }
    for (int idx = tid; idx < 14 * 68; idx += NTHR) {
        int r = idx / 68, c = idx - r * 68;
        int row = (r < 7) ? (49 + r) : (98 + r);      // rows 49..55, 105..111
        KH[row * 68 + c] = make_uint2(0, 0);
    }
    for (int idx = tid; idx < 2 * 128 * VSTR; idx += NTHR)
        VT[idx] = make_uint2(0, 0);

    // ---------------- phase 1a: K and V chunks ----------------
    #pragma unroll 1
    for (int s = 0; s < 4; ++s) {
        const int ci = s + 2;                          // chunks 2,3 = k ; 4,5 = v
        __syncthreads();
        const uint2* gsrc = gW + (size_t)ci * 4096;
        for (int idx = tid; idx < 4096; idx += NTHR)
            WH[(idx >> 6) * 68 + (idx & 63)] = gsrc[idx];
        __syncthreads();
        if (!act) continue;

        float d[4][4] = {};
        mma_dense(XH, WH, d, ra, ra8, wc, t);

        if (s < 2) {
            #pragma unroll
            for (int nb = 0; nb < 4; ++nb) {
                int lc = nh * 32 + nb * 8 + 2 * t;
                int gc = (ci - 2) * 64 + lc;
                float b0 = qkv_b[128 + gc], b1 = qkv_b[129 + gc];
                int wcol = gc >> 1;
                if (v0ok) KH[r0 * 68 + wcol] = split_pack(d[nb][0] + b0, d[nb][1] + b1);
                if (v1ok) KH[r1 * 68 + wcol] = split_pack(d[nb][2] + b0, d[nb][3] + b1);
            }
        } else {
            // V: pair tokens via shfl (lane^4 flips g parity), store u2 into VT
            #pragma unroll
            for (int nb = 0; nb < 4; ++nb) {
                int lc = nh * 32 + nb * 8 + 2 * t;
                int c = (ci - 4) * 64 + lc;
                float b0 = qkv_b[256 + c], b1 = qkv_b[257 + c];
                #pragma unroll
                for (int rr = 0; rr < 2; ++rr) {
                    float vc  = d[nb][2 * rr]     + b0;
                    float vc1 = d[nb][2 * rr + 1] + b1;
                    float oc  = __shfl_xor_sync(0xffffffffu, vc, 4);
                    float oc1 = __shfl_xor_sync(0xffffffffu, vc1, 4);
                    int row = rr ? r1 : r0;
                    int wn = (row >= 56), il = row - 56 * wn;
                    if (!(g & 1) && il < 49) {
                        float e1 = (il + 1 < 49) ? oc  : 0.f;
                        float f1 = (il + 1 < 49) ? oc1 : 0.f;
                        int u = il >> 1;
                        VT[(wn * 128 + c)     * VSTR + u] = split_pack(vc,  e1);
                        VT[(wn * 128 + c + 1) * VSTR + u] = split_pack(vc1, f1);
                    }
                }
            }
        }
    }

    // ---------------- phase 1b: Q chunks (regs), then overwrite XH with q ----------------
    float dq0[4][4] = {}, dq1[4][4] = {};
    __syncthreads();
    for (int idx = tid; idx < 4096; idx += NTHR)
        WH[(idx >> 6) * 68 + (idx & 63)] = gW[idx];
    __syncthreads();
    if (act) mma_dense(XH, WH, dq0, ra, ra8, wc, t);
    __syncthreads();
    for (int idx = tid; idx < 4096; idx += NTHR)
        WH[(idx >> 6) * 68 + (idx & 63)] = gW[4096 + idx];
    __syncthreads();
    if (act) mma_dense(XH, WH, dq1, ra, ra8, wc, t);
    __syncthreads();                                   // all q-mma reads of XH done
    if (act) {
        #pragma unroll
        for (int nb = 0; nb < 4; ++nb) {
            int lc = nh * 32 + nb * 8 + 2 * t;
            {
                int gc = lc;
                float b0 = qkv_b[gc], b1 = qkv_b[gc + 1];
                int wcol = gc >> 1;
                if (v0ok) XH[r0 * 68 + wcol] =
                    split_pack((dq0[nb][0] + b0) * SCALE, (dq0[nb][1] + b1) * SCALE);
                if (v1ok) XH[r1 * 68 + wcol] =
                    split_pack((dq0[nb][2] + b0) * SCALE, (dq0[nb][3] + b1) * SCALE);
            }
            {
                int gc = 64 + lc;
                float b0 = qkv_b[gc], b1 = qkv_b[gc + 1];
                int wcol = gc >> 1;
                if (v0ok) XH[r0 * 68 + wcol] =
                    split_pack((dq1[nb][0] + b0) * SCALE, (dq1[nb][1] + b1) * SCALE);
                if (v1ok) XH[r1 * 68 + wcol] =
                    split_pack((dq1[nb][2] + b0) * SCALE, (dq1[nb][3] + b1) * SCALE);
            }
        }
    }
    __syncthreads();

    // ---------------- phase 2: QK^T (both tasks into regs) ----------------
    float d2[2][7][4];
    #pragma unroll
    for (int it = 0; it < 2; ++it) {
        int task = wid + 16 * it;
        int qwin = task >> 4, rem = task & 15, h = rem >> 2, qt = rem & 3;
        int l0 = qt * 16 + g;
        int qa0 = qwin * 56 + min(l0, 48);
        int qa1 = qwin * 56 + min(l0 + 8, 48);
        #pragma unroll
        for (int jb = 0; jb < 7; ++jb)
            #pragma unroll
            for (int e = 0; e < 4; ++e) d2[it][jb][e] = 0.f;
        #pragma unroll
        for (int kb = 0; kb < 2; ++kb) {
            int kw = h * 16 + kb * 8 + t;
            uint2 a0 = XH[qa0 * 68 + kw];
            uint2 a1 = XH[qa1 * 68 + kw];
            uint2 a2 = XH[qa0 * 68 + kw + 4];
            uint2 a3 = XH[qa1 * 68 + kw + 4];
            unsigned ah[4] = {a0.x, a1.x, a2.x, a3.x};
            unsigned al[4] = {a0.y, a1.y, a2.y, a3.y};
            #pragma unroll
            for (int jb = 0; jb < 7; ++jb) {
                int kr = qwin * 56 + jb * 8 + g;
                mma3(d2[it][jb], ah, al, KH[kr * 68 + kw], KH[kr * 68 + kw + 4]);
            }
        }
    }
    __syncthreads();    // q/k reads complete; attn region (R1+R2) now writable

    // ---------------- phase 3: bias+mask+softmax in regs, write packed attn ----------------
    #pragma unroll
    for (int it = 0; it < 2; ++it) {
        int task = wid + 16 * it;
        int qwin = task >> 4, rem = task & 15, h = rem >> 2, qt = rem & 3;
        const float* maskg = attn_mask + (size_t)((2 * bx + qwin) & 63) * (NTOK * NTOK);
        #pragma unroll
        for (int rr = 0; rr < 2; ++rr) {
            int li = qt * 16 + g + rr * 8;
            bool okr = (li < 49);
            float sv[14];
            float mx = -INFINITY;
            #pragma unroll
            for (int jb = 0; jb < 7; ++jb) {
                #pragma unroll
                for (int e = 0; e < 2; ++e) {
                    int j = jb * 8 + 2 * t + e;
                    float val = -INFINITY;
                    if (okr && j < 49) {
                        int ij = li * 49 + j;
                        val = d2[it][jb][rr * 2 + e]
                            + bias_table[rel_idx[ij] * 4 + h] + maskg[ij];
                    }
                    sv[jb * 2 + e] = val;
                    mx = fmaxf(mx, val);
                }
            }
            mx = fmaxf(mx, __shfl_xor_sync(0xffffffffu, mx, 1));
            mx = fmaxf(mx, __shfl_xor_sync(0xffffffffu, mx, 2));
            float sum = 0.f;
            #pragma unroll
            for (int n = 0; n < 14; ++n) { sv[n] = __expf(sv[n] - mx); sum += sv[n]; }
            sum += __shfl_xor_sync(0xffffffffu, sum, 1);
            sum += __shfl_xor_sync(0xffffffffu, sum, 2);
            float inv = 1.f / sum;
            if (okr) {
                uint2* arow = AT + ((size_t)(qwin * 4 + h) * 49 + li) * 32;
                #pragma unroll
                for (int jb = 0; jb < 7; ++jb)
                    arow[4 * jb + t] = split_pack(sv[2 * jb] * inv, sv[2 * jb + 1] * inv);
                arow[28 + t] = make_uint2(0, 0);        // zero pad cols 28..31
            }
        }
    }
    __syncthreads();

    // ---------------- phase 4: AV -> OV (overlay KH) ----------------
    #pragma unroll
    for (int it = 0; it < 2; ++it) {
        int task = wid + 16 * it;
        int qwin = task >> 4, rem = task & 15, h = rem >> 2, qt = rem & 3;
        int l0 = qt * 16 + g;
        const uint2* ab = AT + (size_t)(qwin * 4 + h) * 49 * 32;
        int qa0 = min(l0, 48), qa1 = min(l0 + 8, 48);
        float d[4][4] = {};
        #pragma unroll
        for (int kb = 0; kb < 4; ++kb) {
            int kw = kb * 8 + t;
            uint2 a0 = ab[qa0 * 32 + kw];
            uint2 a1 = ab[qa1 * 32 + kw];
            uint2 a2 = ab[qa0 * 32 + kw + 4];
            uint2 a3 = ab[qa1 * 32 + kw + 4];
            unsigned ah[4] = {a0.x, a1.x, a2.x, a3.x};
            unsigned al[4] = {a0.y, a1.y, a2.y, a3.y};
            #pragma unroll
            for (int nb = 0; nb < 4; ++nb) {
                int c = 32 * h + nb * 8 + g;
                mma3(d[nb], ah, al, VT[(qwin * 128 + c) * VSTR + kw],
                                    VT[(qwin * 128 + c) * VSTR + kw + 4]);
            }
        }
        #pragma unroll
        for (int nb = 0; nb < 4; ++nb) {
            int cw = 16 * h + nb * 4 + t;
            if (l0 < 49)
                OV[(qwin * 56 + l0) * 68 + cw] = split_pack(d[nb][0], d[nb][1]);
            if (l0 + 8 < 49)
                OV[(qwin * 56 + l0 + 8) * 68 + cw] = split_pack(d[nb][2], d[nb][3]);
        }
    }

    // ---------------- phase 5: proj GEMM (chunks 6,7) ----------------
    #pragma unroll 1
    for (int s = 0; s < 2; ++s) {
        __syncthreads();
        const uint2* gsrc = gW + (size_t)(6 + s) * 4096;
        for (int idx = tid; idx < 4096; idx += NTHR)
            WH[(idx >> 6) * 68 + (idx & 63)] = gsrc[idx];
        __syncthreads();
        if (!act) continue;

        float d[4][4] = {};
        mma_dense(OV, WH, d, ra, ra8, wc, t);

        #pragma unroll
        for (int nb = 0; nb < 4; ++nb) {
            int lc = nh * 32 + nb * 8 + 2 * t;
            int gc = s * 64 + lc;
            float b0 = proj_b[gc], b1 = proj_b[gc + 1];
            if (v0ok)
                *(float2*)(out + ((size_t)(2 * bx + win0) * 49 + i0) * 128 + gc)
                    = make_float2(d[nb][0] + b0, d[nb][1] + b1);
            if (v1ok)
                *(float2*)(out + ((size_t)(2 * bx + win1) * 49 + i1) * 128 + gc)
                    = make_float2(d[nb][2] + b0, d[nb][3] + b1);
        }
    }
}

extern "C" void kernel_launch(void* const* d_in, const int* in_sizes, int n_in,
                              void* d_out, int out_size)
{
    const float* x          = (const float*)d_in[0];
    const float* attn_mask  = (const float*)d_in[1];
    const float* qkv_w      = (const float*)d_in[2];
    const float* qkv_b      = (const float*)d_in[3];
    const float* proj_w     = (const float*)d_in[4];
    const float* proj_b     = (const float*)d_in[5];
    const float* bias_table = (const float*)d_in[6];
    const int*   rel_idx    = (const int*)d_in[7];
    float* out = (float*)d_out;

    prep_kernel<<<64, 512>>>(qkv_w, proj_w);

    const int smem_bytes = SM_U2 * sizeof(uint2);   // 231,424 B
    cudaFuncSetAttribute(wmsa_fused_kernel,
                         cudaFuncAttributeMaxDynamicSharedMemorySize, smem_bytes);

    const int n_windows = in_sizes[0] / (NTOK * 128);   // 4096
    wmsa_fused_kernel<<<n_windows / 2, NTHR, smem_bytes>>>(
        x, attn_mask, qkv_b, proj_b, bias_table, rel_idx, out);
}

// round 9
// speedup vs baseline: 1.2955x; 1.2870x over previous
#include <cuda_runtime.h>

#define SCALE 0.17677669529663687f
#define NTHR  256

// u2 (8-byte) offsets — per-CTA smem = 97,792 B  (2 CTAs/SM)
#define O_X   0        // XH: x -> q packed, 56 x 68 = 3808
#define O_K   3808     // KH: 56 x 68 = 3808       ; AT overlay [0,7056) over XH+KH
#define O_VT  7616     // VT: 128 x 36 = 4608      ; OV (56x68=3808) overlays VT
#define SM_U2 12224

__device__ uint2 gW[512 * 64];   // pre-split weights: col-major cols 0..511, 64 k-words

__device__ __forceinline__ unsigned pack_bf(float x0, float x1) {
    unsigned r;
    asm("cvt.rn.bf16x2.f32 %0, %1, %2;" : "=r"(r) : "f"(x1), "f"(x0));
    return r;
}
__device__ __forceinline__ uint2 split_pack(float x0, float x1) {
    unsigned h = pack_bf(x0, x1);
    float h0 = __uint_as_float(h << 16);
    float h1 = __uint_as_float(h & 0xffff0000u);
    unsigned l = pack_bf(x0 - h0, x1 - h1);
    return make_uint2(h, l);
}
__device__ __forceinline__ void mmabf(float* d, const unsigned* a, const unsigned* b) {
    asm volatile("mma.sync.aligned.m16n8k16.row.col.f32.bf16.bf16.f32 "
        "{%0,%1,%2,%3},{%4,%5,%6,%7},{%8,%9},{%0,%1,%2,%3};"
        : "+f"(d[0]), "+f"(d[1]), "+f"(d[2]), "+f"(d[3])
        : "r"(a[0]), "r"(a[1]), "r"(a[2]), "r"(a[3]), "r"(b[0]), "r"(b[1]));
}
__device__ __forceinline__ void mma3(float* d, const unsigned ah[4], const unsigned al[4],
                                     uint2 b0, uint2 b1) {
    unsigned bh[2] = {b0.x, b1.x};
    unsigned bl[2] = {b0.y, b1.y};
    mmabf(d, ah, bl);
    mmabf(d, al, bh);
    mmabf(d, ah, bh);
}

// Dense stage: warp computes rows rbase+{0,16}+g(+8), cols cb+nb*8.., K=128.
// A in smem (stride 68), B direct from global gB (col*64 + kword).
__device__ __forceinline__ void mma_dense_ldg(const uint2* __restrict__ A,
                                              const uint2* __restrict__ gB,
                                              float d[2][4][4],
                                              int rbase, int cb, int g, int t)
{
    #pragma unroll
    for (int kb = 0; kb < 8; ++kb) {
        const int kw = kb * 8 + t;
        unsigned ah[2][4], al[2][4];
        #pragma unroll
        for (int sub = 0; sub < 2; ++sub) {
            int ra  = min(rbase + sub * 16 + g, 55);
            int ra8 = min(rbase + sub * 16 + 8 + g, 55);
            uint2 a0 = A[ra  * 68 + kw];
            uint2 a1 = A[ra8 * 68 + kw];
            uint2 a2 = A[ra  * 68 + kw + 4];
            uint2 a3 = A[ra8 * 68 + kw + 4];
            ah[sub][0] = a0.x; ah[sub][1] = a1.x; ah[sub][2] = a2.x; ah[sub][3] = a3.x;
            al[sub][0] = a0.y; al[sub][1] = a1.y; al[sub][2] = a2.y; al[sub][3] = a3.y;
        }
        #pragma unroll
        for (int nb = 0; nb < 4; ++nb) {
            uint2 b0 = gB[(cb + nb * 8 + g) * 64 + kw];
            uint2 b1 = gB[(cb + nb * 8 + g) * 64 + kw + 4];
            mma3(d[0][nb], ah[0], al[0], b0, b1);
            mma3(d[1][nb], ah[1], al[1], b0, b1);
        }
    }
}

__global__ void prep_kernel(const float* __restrict__ qkv_w,
                            const float* __restrict__ proj_w)
{
    int idx = blockIdx.x * blockDim.x + threadIdx.x;   // 0..32767
    int c = idx >> 6, u = idx & 63;
    const float* src = (c < 384) ? (qkv_w + (size_t)c * 128)
                                 : (proj_w + (size_t)(c - 384) * 128);
    gW[idx] = split_pack(src[2 * u], src[2 * u + 1]);
}

__global__ __launch_bounds__(NTHR, 2)
void wmsa_fused_kernel(const float* __restrict__ x,
                       const float* __restrict__ attn_mask,
                       const float* __restrict__ qkv_b,
                       const float* __restrict__ proj_b,
                       const float* __restrict__ bias_table,
                       const int*   __restrict__ rel_idx,
                       float* __restrict__ out)
{
    extern __shared__ uint2 smu[];
    uint2* XH = smu + O_X;     // x, then q
    uint2* KH = smu + O_K;
    uint2* VT = smu + O_VT;
    uint2* AT = smu;           // attn overlay over XH+KH
    uint2* OV = smu + O_VT;    // overlay over VT

    const int tid  = threadIdx.x;
    const int bx   = blockIdx.x;
    const int lane = tid & 31;
    const int wid  = tid >> 5;          // 0..7
    const int g    = lane >> 2;
    const int t    = lane & 3;

    // dense-GEMM roles: 2 row-groups x 4 col-quarters
    const int mt2   = wid >> 2;         // 0..1 -> rows mt2*32 ..
    const int nh    = wid & 3;          // cols nh*32 ..
    const int rbase = mt2 * 32;
    const int cb    = nh * 32;

    const float* maskg = attn_mask + (size_t)(bx & 63) * (49 * 49);

    // ---------------- phase 0: load+split x ; zero VT ----------------
    {
        const float2* xg = (const float2*)(x + (size_t)bx * 49 * 128);
        for (int idx = tid; idx < 49 * 64; idx += NTHR) {
            float2 v = xg[idx];
            XH[(idx >> 6) * 68 + (idx & 63)] = split_pack(v.x, v.y);
        }
        for (int idx = tid; idx < 128 * 36; idx += NTHR)
            VT[idx] = make_uint2(0, 0);
    }
    __syncthreads();

    // ---------------- phase 1: K, V, Q (weights via LDG) ----------------
    {   // K
        float d[2][4][4] = {};
        mma_dense_ldg(XH, gW + 128 * 64, d, rbase, cb, g, t);
        #pragma unroll
        for (int sub = 0; sub < 2; ++sub) {
            int r0 = rbase + sub * 16 + g, r1 = r0 + 8;
            #pragma unroll
            for (int nb = 0; nb < 4; ++nb) {
                int c = cb + nb * 8 + 2 * t;
                float b0 = qkv_b[128 + c], b1 = qkv_b[129 + c];
                int wcol = c >> 1;
                if (r0 < 49) KH[r0 * 68 + wcol] = split_pack(d[sub][nb][0] + b0, d[sub][nb][1] + b1);
                if (r1 < 49) KH[r1 * 68 + wcol] = split_pack(d[sub][nb][2] + b0, d[sub][nb][3] + b1);
            }
        }
    }
    {   // V -> VT (transposed, token-paired via shfl)
        float d[2][4][4] = {};
        mma_dense_ldg(XH, gW + 256 * 64, d, rbase, cb, g, t);
        #pragma unroll
        for (int sub = 0; sub < 2; ++sub) {
            #pragma unroll
            for (int nb = 0; nb < 4; ++nb) {
                int c = cb + nb * 8 + 2 * t;
                float b0 = qkv_b[256 + c], b1 = qkv_b[257 + c];
                #pragma unroll
                for (int rr = 0; rr < 2; ++rr) {
                    float vc  = d[sub][nb][2 * rr]     + b0;
                    float vc1 = d[sub][nb][2 * rr + 1] + b1;
                    float oc  = __shfl_xor_sync(0xffffffffu, vc, 4);
                    float oc1 = __shfl_xor_sync(0xffffffffu, vc1, 4);
                    int il = rbase + sub * 16 + rr * 8 + g;
                    if (!(g & 1) && il < 49) {
                        float e1 = (il + 1 < 49) ? oc  : 0.f;
                        float f1 = (il + 1 < 49) ? oc1 : 0.f;
                        int u = il >> 1;
                        VT[c * 36 + u]       = split_pack(vc,  e1);
                        VT[(c + 1) * 36 + u] = split_pack(vc1, f1);
                    }
                }
            }
        }
    }
    {   // Q (compute, sync, then overwrite XH)
        float d[2][4][4] = {};
        mma_dense_ldg(XH, gW, d, rbase, cb, g, t);
        __syncthreads();                      // all XH reads done
        #pragma unroll
        for (int sub = 0; sub < 2; ++sub) {
            int r0 = rbase + sub * 16 + g, r1 = r0 + 8;
            #pragma unroll
            for (int nb = 0; nb < 4; ++nb) {
                int c = cb + nb * 8 + 2 * t;
                float b0 = qkv_b[c], b1 = qkv_b[c + 1];
                int wcol = c >> 1;
                if (r0 < 49) XH[r0 * 68 + wcol] =
                    split_pack((d[sub][nb][0] + b0) * SCALE, (d[sub][nb][1] + b1) * SCALE);
                if (r1 < 49) XH[r1 * 68 + wcol] =
                    split_pack((d[sub][nb][2] + b0) * SCALE, (d[sub][nb][3] + b1) * SCALE);
            }
        }
    }
    __syncthreads();

    // ---------------- phase 2: QK^T into regs (2 tasks/warp) ----------------
    float d2[2][7][4];
    #pragma unroll
    for (int it = 0; it < 2; ++it) {
        int task = wid + 8 * it;              // 0..15
        int h = task >> 2, qt = task & 3;
        int qa0 = min(qt * 16 + g, 48);
        int qa1 = min(qt * 16 + 8 + g, 48);
        #pragma unroll
        for (int jb = 0; jb < 7; ++jb)
            #pragma unroll
            for (int e = 0; e < 4; ++e) d2[it][jb][e] = 0.f;
        #pragma unroll
        for (int kb = 0; kb < 2; ++kb) {
            int kw = h * 16 + kb * 8 + t;
            uint2 a0 = XH[qa0 * 68 + kw];
            uint2 a1 = XH[qa1 * 68 + kw];
            uint2 a2 = XH[qa0 * 68 + kw + 4];
            uint2 a3 = XH[qa1 * 68 + kw + 4];
            unsigned ah[4] = {a0.x, a1.x, a2.x, a3.x};
            unsigned al[4] = {a0.y, a1.y, a2.y, a3.y};
            #pragma unroll
            for (int jb = 0; jb < 7; ++jb) {
                int kr = jb * 8 + g;
                mma3(d2[it][jb], ah, al, KH[kr * 68 + kw], KH[kr * 68 + kw + 4]);
            }
        }
    }
    __syncthreads();                          // XH/KH reads done; AT writable

    // ---------------- phase 3: bias+mask+softmax in regs -> packed AT ----------------
    #pragma unroll
    for (int it = 0; it < 2; ++it) {
        int task = wid + 8 * it;
        int h = task >> 2, qt = task & 3;
        #pragma unroll
        for (int rr = 0; rr < 2; ++rr) {
            int li = qt * 16 + g + rr * 8;
            bool okr = (li < 49);
            float sv[14];
            float mx = -INFINITY;
            #pragma unroll
            for (int jb = 0; jb < 7; ++jb) {
                #pragma unroll
                for (int e = 0; e < 2; ++e) {
                    int j = jb * 8 + 2 * t + e;
                    float val = -INFINITY;
                    if (okr && j < 49) {
                        int ij = li * 49 + j;
                        val = d2[it][jb][rr * 2 + e]
                            + bias_table[rel_idx[ij] * 4 + h] + maskg[ij];
                    }
                    sv[jb * 2 + e] = val;
                    mx = fmaxf(mx, val);
                }
            }
            mx = fmaxf(mx, __shfl_xor_sync(0xffffffffu, mx, 1));
            mx = fmaxf(mx, __shfl_xor_sync(0xffffffffu, mx, 2));
            float sum = 0.f;
            #pragma unroll
            for (int n = 0; n < 14; ++n) { sv[n] = __expf(sv[n] - mx); sum += sv[n]; }
            sum += __shfl_xor_sync(0xffffffffu, sum, 1);
            sum += __shfl_xor_sync(0xffffffffu, sum, 2);
            float inv = 1.f / sum;
            if (okr) {
                uint2* arow = AT + ((size_t)h * 49 + li) * 36;
                #pragma unroll
                for (int jb = 0; jb < 7; ++jb)
                    arow[4 * jb + t] = split_pack(sv[2 * jb] * inv, sv[2 * jb + 1] * inv);
                arow[28 + t] = make_uint2(0, 0);   // zero pad words 28..31
            }
        }
    }
    __syncthreads();

    // ---------------- phase 4: AV into regs, then OV over VT ----------------
    float d4[2][4][4] = {};
    #pragma unroll
    for (int it = 0; it < 2; ++it) {
        int task = wid + 8 * it;
        int h = task >> 2, qt = task & 3;
        const uint2* ab = AT + (size_t)h * 49 * 36;
        int qa0 = min(qt * 16 + g, 48);
        int qa1 = min(qt * 16 + 8 + g, 48);
        #pragma unroll
        for (int kb = 0; kb < 4; ++kb) {
            int kw = kb * 8 + t;
            uint2 a0 = ab[qa0 * 36 + kw];
            uint2 a1 = ab[qa1 * 36 + kw];
            uint2 a2 = ab[qa0 * 36 + kw + 4];
            uint2 a3 = ab[qa1 * 36 + kw + 4];
            unsigned ah[4] = {a0.x, a1.x, a2.x, a3.x};
            unsigned al[4] = {a0.y, a1.y, a2.y, a3.y};
            #pragma unroll
            for (int nb = 0; nb < 4; ++nb) {
                int c = 32 * h + nb * 8 + g;
                mma3(d4[it][nb], ah, al, VT[c * 36 + kw], VT[c * 36 + kw + 4]);
            }
        }
    }
    __syncthreads();                          // VT reads done; OV writable
    #pragma unroll
    for (int it = 0; it < 2; ++it) {
        int task = wid + 8 * it;
        int h = task >> 2, qt = task & 3;
        int l0 = qt * 16 + g;
        #pragma unroll
        for (int nb = 0; nb < 4; ++nb) {
            int cw = 16 * h + nb * 4 + t;
            if (l0 < 49)     OV[l0 * 68 + cw]       = split_pack(d4[it][nb][0], d4[it][nb][1]);
            if (l0 + 8 < 49) OV[(l0 + 8) * 68 + cw] = split_pack(d4[it][nb][2], d4[it][nb][3]);
        }
    }
    __syncthreads();

    // ---------------- phase 5: proj GEMM (weights via LDG) ----------------
    {
        float d[2][4][4] = {};
        mma_dense_ldg(OV, gW + 384 * 64, d, rbase, cb, g, t);
        float* og = out + (size_t)bx * 49 * 128;
        #pragma unroll
        for (int sub = 0; sub < 2; ++sub) {
            int r0 = rbase + sub * 16 + g, r1 = r0 + 8;
            #pragma unroll
            for (int nb = 0; nb < 4; ++nb) {
                int c = cb + nb * 8 + 2 * t;
                float b0 = proj_b[c], b1 = proj_b[c + 1];
                if (r0 < 49)
                    *(float2*)(og + r0 * 128 + c) = make_float2(d[sub][nb][0] + b0, d[sub][nb][1] + b1);
                if (r1 < 49)
                    *(float2*)(og + r1 * 128 + c) = make_float2(d[sub][nb][2] + b0, d[sub][nb][3] + b1);
            }
        }
    }
}

extern "C" void kernel_launch(void* const* d_in, const int* in_sizes, int n_in,
                              void* d_out, int out_size)
{
    const float* x          = (const float*)d_in[0];
    const float* attn_mask  = (const float*)d_in[1];
    const float* qkv_w      = (const float*)d_in[2];
    const float* qkv_b      = (const float*)d_in[3];
    const float* proj_w     = (const float*)d_in[4];
    const float* proj_b     = (const float*)d_in[5];
    const float* bias_table = (const float*)d_in[6];
    const int*   rel_idx    = (const int*)d_in[7];
    float* out = (float*)d_out;

    prep_kernel<<<64, 512>>>(qkv_w, proj_w);

    const int smem_bytes = SM_U2 * sizeof(uint2);     // 97,792 B -> 2 CTAs/SM
    cudaFuncSetAttribute(wmsa_fused_kernel,
                         cudaFuncAttributeMaxDynamicSharedMemorySize, smem_bytes);

    const int n_windows = in_sizes[0] / (49 * 128);   // 4096
    wmsa_fused_kernel<<<n_windows, NTHR, smem_bytes>>>(
        x, attn_mask, qkv_b, proj_b, bias_table, rel_idx, out);
}

// round 10
// speedup vs baseline: 1.3881x; 1.0714x over previous
#include <cuda_runtime.h>

#define SCALE 0.17677669529663687f
#define NTHR  256

// u2 (8-byte) offsets — per-CTA smem = 97,792 B  (2 CTAs/SM)
#define O_X   0        // XH: x -> q packed, 56 x 68 = 3808
#define O_K   3808     // KH: 56 x 68 = 3808       ; AT overlay [0,7056) over XH+KH
#define O_VT  7616     // VT: 128 x 36 = 4608      ; OV (56x68=3808) overlays VT
#define SM_U2 12224

__device__ uint2  gW[512 * 64];            // pre-split weights
__device__ float2 gBM[64 * 4 * 7 * 49 * 4]; // bias+mask table: [wm][h][jb][li][t] -> (j0,j1)

__device__ __forceinline__ unsigned pack_bf(float x0, float x1) {
    unsigned r;
    asm("cvt.rn.bf16x2.f32 %0, %1, %2;" : "=r"(r) : "f"(x1), "f"(x0));
    return r;
}
__device__ __forceinline__ uint2 split_pack(float x0, float x1) {
    unsigned h = pack_bf(x0, x1);
    float h0 = __uint_as_float(h << 16);
    float h1 = __uint_as_float(h & 0xffff0000u);
    unsigned l = pack_bf(x0 - h0, x1 - h1);
    return make_uint2(h, l);
}
__device__ __forceinline__ void mmabf(float* d, const unsigned* a, const unsigned* b) {
    asm volatile("mma.sync.aligned.m16n8k16.row.col.f32.bf16.bf16.f32 "
        "{%0,%1,%2,%3},{%4,%5,%6,%7},{%8,%9},{%0,%1,%2,%3};"
        : "+f"(d[0]), "+f"(d[1]), "+f"(d[2]), "+f"(d[3])
        : "r"(a[0]), "r"(a[1]), "r"(a[2]), "r"(a[3]), "r"(b[0]), "r"(b[1]));
}
__device__ __forceinline__ void mma3(float* d, const unsigned ah[4], const unsigned al[4],
                                     uint2 b0, uint2 b1) {
    unsigned bh[2] = {b0.x, b1.x};
    unsigned bl[2] = {b0.y, b1.y};
    mmabf(d, ah, bl);
    mmabf(d, al, bh);
    mmabf(d, ah, bh);
}

// Dense stage: warp computes rows rbase+{0,16}+g(+8), cols cb+nb*8.., K=128.
__device__ __forceinline__ void mma_dense_ldg(const uint2* __restrict__ A,
                                              const uint2* __restrict__ gB,
                                              float d[2][4][4],
                                              int rbase, int cb, int g, int t)
{
    #pragma unroll
    for (int kb = 0; kb < 8; ++kb) {
        const int kw = kb * 8 + t;
        unsigned ah[2][4], al[2][4];
        #pragma unroll
        for (int sub = 0; sub < 2; ++sub) {
            int ra  = min(rbase + sub * 16 + g, 55);
            int ra8 = min(rbase + sub * 16 + 8 + g, 55);
            uint2 a0 = A[ra  * 68 + kw];
            uint2 a1 = A[ra8 * 68 + kw];
            uint2 a2 = A[ra  * 68 + kw + 4];
            uint2 a3 = A[ra8 * 68 + kw + 4];
            ah[sub][0] = a0.x; ah[sub][1] = a1.x; ah[sub][2] = a2.x; ah[sub][3] = a3.x;
            al[sub][0] = a0.y; al[sub][1] = a1.y; al[sub][2] = a2.y; al[sub][3] = a3.y;
        }
        #pragma unroll
        for (int nb = 0; nb < 4; ++nb) {
            uint2 b0 = gB[(cb + nb * 8 + g) * 64 + kw];
            uint2 b1 = gB[(cb + nb * 8 + g) * 64 + kw + 4];
            mma3(d[0][nb], ah[0], al[0], b0, b1);
            mma3(d[1][nb], ah[1], al[1], b0, b1);
        }
    }
}

__global__ void prep_kernel(const float* __restrict__ qkv_w,
                            const float* __restrict__ proj_w)
{
    int idx = blockIdx.x * blockDim.x + threadIdx.x;   // 0..32767
    int c = idx >> 6, u = idx & 63;
    const float* src = (c < 384) ? (qkv_w + (size_t)c * 128)
                                 : (proj_w + (size_t)(c - 384) * 128);
    gW[idx] = split_pack(src[2 * u], src[2 * u + 1]);
}

// BM[wm][h][jb][li][t] = (bias+mask) for (li, j=jb*8+2t), (li, j+1); -1e30 pads.
__global__ void prep_bm(const float* __restrict__ attn_mask,
                        const float* __restrict__ bias_table,
                        const int*   __restrict__ rel_idx)
{
    int idx = blockIdx.x * blockDim.x + threadIdx.x;
    if (idx >= 64 * 4 * 7 * 49 * 4) return;
    int t  = idx & 3;
    int q  = idx >> 2;
    int li = q % 49;   q /= 49;
    int jb = q % 7;    q /= 7;
    int h  = q & 3;
    int wm = q >> 2;
    int j0 = jb * 8 + 2 * t;
    float v0 = -1e30f, v1 = -1e30f;
    if (j0 < 49)
        v0 = bias_table[rel_idx[li * 49 + j0] * 4 + h] + attn_mask[wm * 2401 + li * 49 + j0];
    if (j0 + 1 < 49)
        v1 = bias_table[rel_idx[li * 49 + j0 + 1] * 4 + h] + attn_mask[wm * 2401 + li * 49 + j0 + 1];
    gBM[idx] = make_float2(v0, v1);
}

__global__ __launch_bounds__(NTHR, 2)
void wmsa_fused_kernel(const float* __restrict__ x,
                       const float* __restrict__ qkv_b,
                       const float* __restrict__ proj_b,
                       float* __restrict__ out)
{
    extern __shared__ uint2 smu[];
    uint2* XH = smu + O_X;     // x, then q
    uint2* KH = smu + O_K;
    uint2* VT = smu + O_VT;
    uint2* AT = smu;           // attn overlay over XH+KH
    uint2* OV = smu + O_VT;    // overlay over VT

    const int tid  = threadIdx.x;
    const int bx   = blockIdx.x;
    const int lane = tid & 31;
    const int wid  = tid >> 5;          // 0..7
    const int g    = lane >> 2;
    const int t    = lane & 3;

    const int mt2   = wid >> 2;         // 0..1 -> rows mt2*32 ..
    const int nh    = wid & 3;          // cols nh*32 ..
    const int rbase = mt2 * 32;
    const int cb    = nh * 32;

    // ---------------- phase 0: load+split x ; zero VT + KH pads ----------------
    {
        const float2* xg = (const float2*)(x + (size_t)bx * 49 * 128);
        for (int idx = tid; idx < 49 * 64; idx += NTHR) {
            float2 v = xg[idx];
            XH[(idx >> 6) * 68 + (idx & 63)] = split_pack(v.x, v.y);
        }
        for (int idx = tid; idx < 128 * 36; idx += NTHR)
            VT[idx] = make_uint2(0, 0);
        for (int idx = tid; idx < 7 * 68; idx += NTHR)      // KH rows 49..55 = 0
            KH[49 * 68 + idx] = make_uint2(0, 0);
    }
    __syncthreads();

    // ---------------- phase 1: K, V, Q (weights via LDG) ----------------
    {   // K
        float d[2][4][4] = {};
        mma_dense_ldg(XH, gW + 128 * 64, d, rbase, cb, g, t);
        #pragma unroll
        for (int sub = 0; sub < 2; ++sub) {
            int r0 = rbase + sub * 16 + g, r1 = r0 + 8;
            #pragma unroll
            for (int nb = 0; nb < 4; ++nb) {
                int c = cb + nb * 8 + 2 * t;
                float b0 = qkv_b[128 + c], b1 = qkv_b[129 + c];
                int wcol = c >> 1;
                if (r0 < 49) KH[r0 * 68 + wcol] = split_pack(d[sub][nb][0] + b0, d[sub][nb][1] + b1);
                if (r1 < 49) KH[r1 * 68 + wcol] = split_pack(d[sub][nb][2] + b0, d[sub][nb][3] + b1);
            }
        }
    }
    {   // V -> VT (transposed, token-paired via shfl)
        float d[2][4][4] = {};
        mma_dense_ldg(XH, gW + 256 * 64, d, rbase, cb, g, t);
        #pragma unroll
        for (int sub = 0; sub < 2; ++sub) {
            #pragma unroll
            for (int nb = 0; nb < 4; ++nb) {
                int c = cb + nb * 8 + 2 * t;
                float b0 = qkv_b[256 + c], b1 = qkv_b[257 + c];
                #pragma unroll
                for (int rr = 0; rr < 2; ++rr) {
                    float vc  = d[sub][nb][2 * rr]     + b0;
                    float vc1 = d[sub][nb][2 * rr + 1] + b1;
                    float oc  = __shfl_xor_sync(0xffffffffu, vc, 4);
                    float oc1 = __shfl_xor_sync(0xffffffffu, vc1, 4);
                    int il = rbase + sub * 16 + rr * 8 + g;
                    if (!(g & 1) && il < 49) {
                        float e1 = (il + 1 < 49) ? oc  : 0.f;
                        float f1 = (il + 1 < 49) ? oc1 : 0.f;
                        int u = il >> 1;
                        VT[c * 36 + u]       = split_pack(vc,  e1);
                        VT[(c + 1) * 36 + u] = split_pack(vc1, f1);
                    }
                }
            }
        }
    }
    {   // Q (compute, sync, then overwrite XH)
        float d[2][4][4] = {};
        mma_dense_ldg(XH, gW, d, rbase, cb, g, t);
        __syncthreads();                      // all XH reads done
        #pragma unroll
        for (int sub = 0; sub < 2; ++sub) {
            int r0 = rbase + sub * 16 + g, r1 = r0 + 8;
            #pragma unroll
            for (int nb = 0; nb < 4; ++nb) {
                int c = cb + nb * 8 + 2 * t;
                float b0 = qkv_b[c], b1 = qkv_b[c + 1];
                int wcol = c >> 1;
                if (r0 < 49) XH[r0 * 68 + wcol] =
                    split_pack((d[sub][nb][0] + b0) * SCALE, (d[sub][nb][1] + b1) * SCALE);
                if (r1 < 49) XH[r1 * 68 + wcol] =
                    split_pack((d[sub][nb][2] + b0) * SCALE, (d[sub][nb][3] + b1) * SCALE);
            }
        }
    }
    __syncthreads();

    // ---------------- phase 2: QK^T into regs (2 tasks/warp) ----------------
    float d2[2][7][4];
    #pragma unroll
    for (int it = 0; it < 2; ++it) {
        int task = wid + 8 * it;              // 0..15
        int h = task >> 2, qt = task & 3;
        int qa0 = min(qt * 16 + g, 48);
        int qa1 = min(qt * 16 + 8 + g, 48);
        #pragma unroll
        for (int jb = 0; jb < 7; ++jb)
            #pragma unroll
            for (int e = 0; e < 4; ++e) d2[it][jb][e] = 0.f;
        #pragma unroll
        for (int kb = 0; kb < 2; ++kb) {
            int kw = h * 16 + kb * 8 + t;
            uint2 a0 = XH[qa0 * 68 + kw];
            uint2 a1 = XH[qa1 * 68 + kw];
            uint2 a2 = XH[qa0 * 68 + kw + 4];
            uint2 a3 = XH[qa1 * 68 + kw + 4];
            unsigned ah[4] = {a0.x, a1.x, a2.x, a3.x};
            unsigned al[4] = {a0.y, a1.y, a2.y, a3.y};
            #pragma unroll
            for (int jb = 0; jb < 7; ++jb) {
                int kr = jb * 8 + g;
                mma3(d2[it][jb], ah, al, KH[kr * 68 + kw], KH[kr * 68 + kw + 4]);
            }
        }
    }
    __syncthreads();                          // XH/KH reads done; AT writable

    // ---------------- phase 3: folded bias+mask (coalesced) + softmax -> AT ----------------
    #pragma unroll
    for (int it = 0; it < 2; ++it) {
        int task = wid + 8 * it;
        int h = task >> 2, qt = task & 3;
        const float2* bmh = gBM + ((size_t)(bx & 63) * 4 + h) * (7 * 49 * 4);
        #pragma unroll
        for (int rr = 0; rr < 2; ++rr) {
            int li = qt * 16 + rr * 8 + g;
            bool okr = (li < 49);
            int lic = min(li, 48);
            float sv[14];
            float mx = -INFINITY;
            #pragma unroll
            for (int jb = 0; jb < 7; ++jb) {
                float2 bm = bmh[(jb * 49 + lic) * 4 + t];   // 256B coalesced across warp
                float v0 = d2[it][jb][rr * 2]     + bm.x;
                float v1 = d2[it][jb][rr * 2 + 1] + bm.y;
                sv[2 * jb]     = v0;
                sv[2 * jb + 1] = v1;
                mx = fmaxf(mx, fmaxf(v0, v1));
            }
            mx = fmaxf(mx, __shfl_xor_sync(0xffffffffu, mx, 1));
            mx = fmaxf(mx, __shfl_xor_sync(0xffffffffu, mx, 2));
            float sum = 0.f;
            #pragma unroll
            for (int n = 0; n < 14; ++n) { sv[n] = __expf(sv[n] - mx); sum += sv[n]; }
            sum += __shfl_xor_sync(0xffffffffu, sum, 1);
            sum += __shfl_xor_sync(0xffffffffu, sum, 2);
            float inv = 1.f / sum;
            if (okr) {
                uint2* arow = AT + ((size_t)h * 49 + li) * 36;
                #pragma unroll
                for (int jb = 0; jb < 7; ++jb)
                    arow[4 * jb + t] = split_pack(sv[2 * jb] * inv, sv[2 * jb + 1] * inv);
                arow[28 + t] = make_uint2(0, 0);   // zero pad words 28..31
            }
        }
    }
    __syncthreads();

    // ---------------- phase 4: AV into regs, then OV over VT ----------------
    float d4[2][4][4] = {};
    #pragma unroll
    for (int it = 0; it < 2; ++it) {
        int task = wid + 8 * it;
        int h = task >> 2, qt = task & 3;
        const uint2* ab = AT + (size_t)h * 49 * 36;
        int qa0 = min(qt * 16 + g, 48);
        int qa1 = min(qt * 16 + 8 + g, 48);
        #pragma unroll
        for (int kb = 0; kb < 4; ++kb) {
            int kw = kb * 8 + t;
            uint2 a0 = ab[qa0 * 36 + kw];
            uint2 a1 = ab[qa1 * 36 + kw];
            uint2 a2 = ab[qa0 * 36 + kw + 4];
            uint2 a3 = ab[qa1 * 36 + kw + 4];
            unsigned ah[4] = {a0.x, a1.x, a2.x, a3.x};
            unsigned al[4] = {a0.y, a1.y, a2.y, a3.y};
            #pragma unroll
            for (int nb = 0; nb < 4; ++nb) {
                int c = 32 * h + nb * 8 + g;
                mma3(d4[it][nb], ah, al, VT[c * 36 + kw], VT[c * 36 + kw + 4]);
            }
        }
    }
    __syncthreads();                          // VT reads done; OV writable
    #pragma unroll
    for (int it = 0; it < 2; ++it) {
        int task = wid + 8 * it;
        int h = task >> 2, qt = task & 3;
        int l0 = qt * 16 + g;
        #pragma unroll
        for (int nb = 0; nb < 4; ++nb) {
            int cw = 16 * h + nb * 4 + t;
            if (l0 < 49)     OV[l0 * 68 + cw]       = split_pack(d4[it][nb][0], d4[it][nb][1]);
            if (l0 + 8 < 49) OV[(l0 + 8) * 68 + cw] = split_pack(d4[it][nb][2], d4[it][nb][3]);
        }
    }
    __syncthreads();

    // ---------------- phase 5: proj GEMM (weights via LDG) ----------------
    {
        float d[2][4][4] = {};
        mma_dense_ldg(OV, gW + 384 * 64, d, rbase, cb, g, t);
        float* og = out + (size_t)bx * 49 * 128;
        #pragma unroll
        for (int sub = 0; sub < 2; ++sub) {
            int r0 = rbase + sub * 16 + g, r1 = r0 + 8;
            #pragma unroll
            for (int nb = 0; nb < 4; ++nb) {
                int c = cb + nb * 8 + 2 * t;
                float b0 = proj_b[c], b1 = proj_b[c + 1];
                if (r0 < 49)
                    *(float2*)(og + r0 * 128 + c) = make_float2(d[sub][nb][0] + b0, d[sub][nb][1] + b1);
                if (r1 < 49)
                    *(float2*)(og + r1 * 128 + c) = make_float2(d[sub][nb][2] + b0, d[sub][nb][3] + b1);
            }
        }
    }
}

extern "C" void kernel_launch(void* const* d_in, const int* in_sizes, int n_in,
                              void* d_out, int out_size)
{
    const float* x          = (const float*)d_in[0];
    const float* attn_mask  = (const float*)d_in[1];
    const float* qkv_w      = (const float*)d_in[2];
    const float* qkv_b      = (const float*)d_in[3];
    const float* proj_w     = (const float*)d_in[4];
    const float* proj_b     = (const float*)d_in[5];
    const float* bias_table = (const float*)d_in[6];
    const int*   rel_idx    = (const int*)d_in[7];
    float* out = (float*)d_out;

    prep_kernel<<<64, 512>>>(qkv_w, proj_w);
    prep_bm<<<(64 * 4 * 7 * 49 * 4 + 255) / 256, 256>>>(attn_mask, bias_table, rel_idx);

    const int smem_bytes = SM_U2 * sizeof(uint2);     // 97,792 B -> 2 CTAs/SM
    cudaFuncSetAttribute(wmsa_fused_kernel,
                         cudaFuncAttributeMaxDynamicSharedMemorySize, smem_bytes);

    const int n_windows = in_sizes[0] / (49 * 128);   // 4096
    wmsa_fused_kernel<<<n_windows, NTHR, smem_bytes>>>(x, qkv_b, proj_b, out);
}

// round 11
// speedup vs baseline: 1.5574x; 1.1220x over previous
#include <cuda_runtime.h>

#define SCALE 0.17677669529663687f
#define NTHR  256

// u2 (8-byte) offsets — per-CTA smem = 97,792 B  (2 CTAs/SM)
#define O_X   0        // XH: x -> q packed, 56 x 68 = 3808
#define O_K   3808     // KH: 56 x 68 = 3808       ; AT overlay [0,7056) over XH+KH
#define O_VT  7616     // VT: 128 x 36 = 4608      ; OV (56x68=3808) overlays VT
#define SM_U2 12224

// fragment-major pre-split weights:
// gW4[colblk(64)][kb(8)][g(8)][t(4)] = uint4{hi(kb*8+t), lo(kb*8+t), hi(kb*8+t+4), lo(kb*8+t+4)}
// for col = colblk*8 + g.  One warp fragment = 32 consecutive uint4 = 512B coalesced.
__device__ uint4  gW4[64 * 8 * 8 * 4];
__device__ float2 gBM[64 * 4 * 7 * 49 * 4]; // bias+mask: [wm][h][jb][li][t] -> (j0,j1)

__device__ __forceinline__ unsigned pack_bf(float x0, float x1) {
    unsigned r;
    asm("cvt.rn.bf16x2.f32 %0, %1, %2;" : "=r"(r) : "f"(x1), "f"(x0));
    return r;
}
__device__ __forceinline__ uint2 split_pack(float x0, float x1) {
    unsigned h = pack_bf(x0, x1);
    float h0 = __uint_as_float(h << 16);
    float h1 = __uint_as_float(h & 0xffff0000u);
    unsigned l = pack_bf(x0 - h0, x1 - h1);
    return make_uint2(h, l);
}
__device__ __forceinline__ void mmabf(float* d, const unsigned* a, const unsigned* b) {
    asm volatile("mma.sync.aligned.m16n8k16.row.col.f32.bf16.bf16.f32 "
        "{%0,%1,%2,%3},{%4,%5,%6,%7},{%8,%9},{%0,%1,%2,%3};"
        : "+f"(d[0]), "+f"(d[1]), "+f"(d[2]), "+f"(d[3])
        : "r"(a[0]), "r"(a[1]), "r"(a[2]), "r"(a[3]), "r"(b[0]), "r"(b[1]));
}
__device__ __forceinline__ void mma3(float* d, const unsigned ah[4], const unsigned al[4],
                                     uint2 b0, uint2 b1) {
    unsigned bh[2] = {b0.x, b1.x};
    unsigned bl[2] = {b0.y, b1.y};
    mmabf(d, ah, bl);
    mmabf(d, al, bh);
    mmabf(d, ah, bh);
}

// Dense stage: warp computes rows rbase+{0,16}+g(+8), cols cb+nb*8.., K=128.
// A in smem (stride 68); B fragment-major from global (gBw pre-offset by col block).
__device__ __forceinline__ void mma_dense_ldg(const uint2* __restrict__ A,
                                              const uint4* __restrict__ gBw,
                                              float d[2][4][4],
                                              int rbase, int g, int t, int lane)
{
    #pragma unroll
    for (int kb = 0; kb < 8; ++kb) {
        const int kw = kb * 8 + t;
        unsigned ah[2][4], al[2][4];
        #pragma unroll
        for (int sub = 0; sub < 2; ++sub) {
            int ra  = min(rbase + sub * 16 + g, 55);
            int ra8 = min(rbase + sub * 16 + 8 + g, 55);
            uint2 a0 = A[ra  * 68 + kw];
            uint2 a1 = A[ra8 * 68 + kw];
            uint2 a2 = A[ra  * 68 + kw + 4];
            uint2 a3 = A[ra8 * 68 + kw + 4];
            ah[sub][0] = a0.x; ah[sub][1] = a1.x; ah[sub][2] = a2.x; ah[sub][3] = a3.x;
            al[sub][0] = a0.y; al[sub][1] = a1.y; al[sub][2] = a2.y; al[sub][3] = a3.y;
        }
        #pragma unroll
        for (int nb = 0; nb < 4; ++nb) {
            uint4 f = gBw[nb * 256 + kb * 32 + lane];   // 512B coalesced per warp
            uint2 b0 = make_uint2(f.x, f.y);
            uint2 b1 = make_uint2(f.z, f.w);
            mma3(d[0][nb], ah[0], al[0], b0, b1);
            mma3(d[1][nb], ah[1], al[1], b0, b1);
        }
    }
}

__global__ void prep_kernel(const float* __restrict__ qkv_w,
                            const float* __restrict__ proj_w)
{
    int idx = blockIdx.x * blockDim.x + threadIdx.x;   // 0..16383
    if (idx >= 64 * 8 * 8 * 4) return;
    int t    = idx & 3;
    int g    = (idx >> 2) & 7;
    int kb   = (idx >> 5) & 7;
    int cblk = idx >> 8;
    int col  = cblk * 8 + g;
    const float* src = (col < 384) ? (qkv_w + (size_t)col * 128)
                                   : (proj_w + (size_t)(col - 384) * 128);
    int w0 = kb * 8 + t;
    int w1 = w0 + 4;
    uint2 p0 = split_pack(src[2 * w0], src[2 * w0 + 1]);
    uint2 p1 = split_pack(src[2 * w1], src[2 * w1 + 1]);
    gW4[idx] = make_uint4(p0.x, p0.y, p1.x, p1.y);
}

// BM[wm][h][jb][li][t] = (bias+mask) for (li, j=jb*8+2t), (li, j+1); -1e30 pads.
__global__ void prep_bm(const float* __restrict__ attn_mask,
                        const float* __restrict__ bias_table,
                        const int*   __restrict__ rel_idx)
{
    int idx = blockIdx.x * blockDim.x + threadIdx.x;
    if (idx >= 64 * 4 * 7 * 49 * 4) return;
    int t  = idx & 3;
    int q  = idx >> 2;
    int li = q % 49;   q /= 49;
    int jb = q % 7;    q /= 7;
    int h  = q & 3;
    int wm = q >> 2;
    int j0 = jb * 8 + 2 * t;
    float v0 = -1e30f, v1 = -1e30f;
    if (j0 < 49)
        v0 = bias_table[rel_idx[li * 49 + j0] * 4 + h] + attn_mask[wm * 2401 + li * 49 + j0];
    if (j0 + 1 < 49)
        v1 = bias_table[rel_idx[li * 49 + j0 + 1] * 4 + h] + attn_mask[wm * 2401 + li * 49 + j0 + 1];
    gBM[idx] = make_float2(v0, v1);
}

__global__ __launch_bounds__(NTHR, 2)
void wmsa_fused_kernel(const float* __restrict__ x,
                       const float* __restrict__ qkv_b,
                       const float* __restrict__ proj_b,
                       float* __restrict__ out)
{
    extern __shared__ uint2 smu[];
    uint2* XH = smu + O_X;     // x, then q
    uint2* KH = smu + O_K;
    uint2* VT = smu + O_VT;
    uint2* AT = smu;           // attn overlay over XH+KH
    uint2* OV = smu + O_VT;    // overlay over VT

    const int tid  = threadIdx.x;
    const int bx   = blockIdx.x;
    const int lane = tid & 31;
    const int wid  = tid >> 5;          // 0..7
    const int g    = lane >> 2;
    const int t    = lane & 3;

    const int mt2   = wid >> 2;         // 0..1 -> rows mt2*32 ..
    const int nh    = wid & 3;          // cols nh*32 ..
    const int rbase = mt2 * 32;
    const int cb    = nh * 32;
    const uint4* gBq = gW4 + (cb >> 3) * 256;   // this warp's col-block base

    // ---------------- phase 0: load+split x ; zero VT + KH pads ----------------
    {
        const float2* xg = (const float2*)(x + (size_t)bx * 49 * 128);
        for (int idx = tid; idx < 49 * 64; idx += NTHR) {
            float2 v = xg[idx];
            XH[(idx >> 6) * 68 + (idx & 63)] = split_pack(v.x, v.y);
        }
        for (int idx = tid; idx < 128 * 36; idx += NTHR)
            VT[idx] = make_uint2(0, 0);
        for (int idx = tid; idx < 7 * 68; idx += NTHR)      // KH rows 49..55 = 0
            KH[49 * 68 + idx] = make_uint2(0, 0);
    }
    __syncthreads();

    // ---------------- phase 1: K, V, Q (weights via coalesced LDG.128) ----------------
    {   // K (col block 16 of gW4)
        float d[2][4][4] = {};
        mma_dense_ldg(XH, gBq + 16 * 256, d, rbase, g, t, lane);
        #pragma unroll
        for (int sub = 0; sub < 2; ++sub) {
            int r0 = rbase + sub * 16 + g, r1 = r0 + 8;
            #pragma unroll
            for (int nb = 0; nb < 4; ++nb) {
                int c = cb + nb * 8 + 2 * t;
                float b0 = qkv_b[128 + c], b1 = qkv_b[129 + c];
                int wcol = c >> 1;
                if (r0 < 49) KH[r0 * 68 + wcol] = split_pack(d[sub][nb][0] + b0, d[sub][nb][1] + b1);
                if (r1 < 49) KH[r1 * 68 + wcol] = split_pack(d[sub][nb][2] + b0, d[sub][nb][3] + b1);
            }
        }
    }
    {   // V (col block 32) -> VT (transposed, token-paired via shfl)
        float d[2][4][4] = {};
        mma_dense_ldg(XH, gBq + 32 * 256, d, rbase, g, t, lane);
        #pragma unroll
        for (int sub = 0; sub < 2; ++sub) {
            #pragma unroll
            for (int nb = 0; nb < 4; ++nb) {
                int c = cb + nb * 8 + 2 * t;
                float b0 = qkv_b[256 + c], b1 = qkv_b[257 + c];
                #pragma unroll
                for (int rr = 0; rr < 2; ++rr) {
                    float vc  = d[sub][nb][2 * rr]     + b0;
                    float vc1 = d[sub][nb][2 * rr + 1] + b1;
                    float oc  = __shfl_xor_sync(0xffffffffu, vc, 4);
                    float oc1 = __shfl_xor_sync(0xffffffffu, vc1, 4);
                    int il = rbase + sub * 16 + rr * 8 + g;
                    if (!(g & 1) && il < 49) {
                        float e1 = (il + 1 < 49) ? oc  : 0.f;
                        float f1 = (il + 1 < 49) ? oc1 : 0.f;
                        int u = il >> 1;
                        VT[c * 36 + u]       = split_pack(vc,  e1);
                        VT[(c + 1) * 36 + u] = split_pack(vc1, f1);
                    }
                }
            }
        }
    }
    {   // Q (col block 0): compute, sync, then overwrite XH
        float d[2][4][4] = {};
        mma_dense_ldg(XH, gBq, d, rbase, g, t, lane);
        __syncthreads();                      // all XH reads done
        #pragma unroll
        for (int sub = 0; sub < 2; ++sub) {
            int r0 = rbase + sub * 16 + g, r1 = r0 + 8;
            #pragma unroll
            for (int nb = 0; nb < 4; ++nb) {
                int c = cb + nb * 8 + 2 * t;
                float b0 = qkv_b[c], b1 = qkv_b[c + 1];
                int wcol = c >> 1;
                if (r0 < 49) XH[r0 * 68 + wcol] =
                    split_pack((d[sub][nb][0] + b0) * SCALE, (d[sub][nb][1] + b1) * SCALE);
                if (r1 < 49) XH[r1 * 68 + wcol] =
                    split_pack((d[sub][nb][2] + b0) * SCALE, (d[sub][nb][3] + b1) * SCALE);
            }
        }
    }
    __syncthreads();

    // ---------------- phase 2: QK^T into regs (2 tasks/warp) ----------------
    float d2[2][7][4];
    #pragma unroll
    for (int it = 0; it < 2; ++it) {
        int task = wid + 8 * it;              // 0..15
        int h = task >> 2, qt = task & 3;
        int qa0 = min(qt * 16 + g, 48);
        int qa1 = min(qt * 16 + 8 + g, 48);
        #pragma unroll
        for (int jb = 0; jb < 7; ++jb)
            #pragma unroll
            for (int e = 0; e < 4; ++e) d2[it][jb][e] = 0.f;
        #pragma unroll
        for (int kb = 0; kb < 2; ++kb) {
            int kw = h * 16 + kb * 8 + t;
            uint2 a0 = XH[qa0 * 68 + kw];
            uint2 a1 = XH[qa1 * 68 + kw];
            uint2 a2 = XH[qa0 * 68 + kw + 4];
            uint2 a3 = XH[qa1 * 68 + kw + 4];
            unsigned ah[4] = {a0.x, a1.x, a2.x, a3.x};
            unsigned al[4] = {a0.y, a1.y, a2.y, a3.y};
            #pragma unroll
            for (int jb = 0; jb < 7; ++jb) {
                int kr = jb * 8 + g;
                mma3(d2[it][jb], ah, al, KH[kr * 68 + kw], KH[kr * 68 + kw + 4]);
            }
        }
    }
    __syncthreads();                          // XH/KH reads done; AT writable

    // ---------------- phase 3: folded bias+mask (coalesced) + softmax -> AT ----------------
    #pragma unroll
    for (int it = 0; it < 2; ++it) {
        int task = wid + 8 * it;
        int h = task >> 2, qt = task & 3;
        const float2* bmh = gBM + ((size_t)(bx & 63) * 4 + h) * (7 * 49 * 4);
        #pragma unroll
        for (int rr = 0; rr < 2; ++rr) {
            int li = qt * 16 + rr * 8 + g;
            bool okr = (li < 49);
            int lic = min(li, 48);
            float sv[14];
            float mx = -INFINITY;
            #pragma unroll
            for (int jb = 0; jb < 7; ++jb) {
                float2 bm = bmh[(jb * 49 + lic) * 4 + t];   // 256B coalesced across warp
                float v0 = d2[it][jb][rr * 2]     + bm.x;
                float v1 = d2[it][jb][rr * 2 + 1] + bm.y;
                sv[2 * jb]     = v0;
                sv[2 * jb + 1] = v1;
                mx = fmaxf(mx, fmaxf(v0, v1));
            }
            mx = fmaxf(mx, __shfl_xor_sync(0xffffffffu, mx, 1));
            mx = fmaxf(mx, __shfl_xor_sync(0xffffffffu, mx, 2));
            float sum = 0.f;
            #pragma unroll
            for (int n = 0; n < 14; ++n) { sv[n] = __expf(sv[n] - mx); sum += sv[n]; }
            sum += __shfl_xor_sync(0xffffffffu, sum, 1);
            sum += __shfl_xor_sync(0xffffffffu, sum, 2);
            float inv = 1.f / sum;
            if (okr) {
                uint2* arow = AT + ((size_t)h * 49 + li) * 36;
                #pragma unroll
                for (int jb = 0; jb < 7; ++jb)
                    arow[4 * jb + t] = split_pack(sv[2 * jb] * inv, sv[2 * jb + 1] * inv);
                arow[28 + t] = make_uint2(0, 0);   // zero pad words 28..31
            }
        }
    }
    __syncthreads();

    // ---------------- phase 4: AV into regs, then OV over VT ----------------
    float d4[2][4][4] = {};
    #pragma unroll
    for (int it = 0; it < 2; ++it) {
        int task = wid + 8 * it;
        int h = task >> 2, qt = task & 3;
        const uint2* ab = AT + (size_t)h * 49 * 36;
        int qa0 = min(qt * 16 + g, 48);
        int qa1 = min(qt * 16 + 8 + g, 48);
        #pragma unroll
        for (int kb = 0; kb < 4; ++kb) {
            int kw = kb * 8 + t;
            uint2 a0 = ab[qa0 * 36 + kw];
            uint2 a1 = ab[qa1 * 36 + kw];
            uint2 a2 = ab[qa0 * 36 + kw + 4];
            uint2 a3 = ab[qa1 * 36 + kw + 4];
            unsigned ah[4] = {a0.x, a1.x, a2.x, a3.x};
            unsigned al[4] = {a0.y, a1.y, a2.y, a3.y};
            #pragma unroll
            for (int nb = 0; nb < 4; ++nb) {
                int c = 32 * h + nb * 8 + g;
                mma3(d4[it][nb], ah, al, VT[c * 36 + kw], VT[c * 36 + kw + 4]);
            }
        }
    }
    __syncthreads();                          // VT reads done; OV writable
    #pragma unroll
    for (int it = 0; it < 2; ++it) {
        int task = wid + 8 * it;
        int h = task >> 2, qt = task & 3;
        int l0 = qt * 16 + g;
        #pragma unroll
        for (int nb = 0; nb < 4; ++nb) {
            int cw = 16 * h + nb * 4 + t;
            if (l0 < 49)     OV[l0 * 68 + cw]       = split_pack(d4[it][nb][0], d4[it][nb][1]);
            if (l0 + 8 < 49) OV[(l0 + 8) * 68 + cw] = split_pack(d4[it][nb][2], d4[it][nb][3]);
        }
    }
    __syncthreads();

    // ---------------- phase 5: proj GEMM (col block 48) ----------------
    {
        float d[2][4][4] = {};
        mma_dense_ldg(OV, gBq + 48 * 256, d, rbase, g, t, lane);
        float* og = out + (size_t)bx * 49 * 128;
        #pragma unroll
        for (int sub = 0; sub < 2; ++sub) {
            int r0 = rbase + sub * 16 + g, r1 = r0 + 8;
            #pragma unroll
            for (int nb = 0; nb < 4; ++nb) {
                int c = cb + nb * 8 + 2 * t;
                float b0 = proj_b[c], b1 = proj_b[c + 1];
                if (r0 < 49)
                    *(float2*)(og + r0 * 128 + c) = make_float2(d[sub][nb][0] + b0, d[sub][nb][1] + b1);
                if (r1 < 49)
                    *(float2*)(og + r1 * 128 + c) = make_float2(d[sub][nb][2] + b0, d[sub][nb][3] + b1);
            }
        }
    }
}

extern "C" void kernel_launch(void* const* d_in, const int* in_sizes, int n_in,
                              void* d_out, int out_size)
{
    const float* x          = (const float*)d_in[0];
    const float* attn_mask  = (const float*)d_in[1];
    const float* qkv_w      = (const float*)d_in[2];
    const float* qkv_b      = (const float*)d_in[3];
    const float* proj_w     = (const float*)d_in[4];
    const float* proj_b     = (const float*)d_in[5];
    const float* bias_table = (const float*)d_in[6];
    const int*   rel_idx    = (const int*)d_in[7];
    float* out = (float*)d_out;

    prep_kernel<<<(64 * 8 * 8 * 4 + 255) / 256, 256>>>(qkv_w, proj_w);
    prep_bm<<<(64 * 4 * 7 * 49 * 4 + 255) / 256, 256>>>(attn_mask, bias_table, rel_idx);

    const int smem_bytes = SM_U2 * sizeof(uint2);     // 97,792 B -> 2 CTAs/SM
    cudaFuncSetAttribute(wmsa_fused_kernel,
                         cudaFuncAttributeMaxDynamicSharedMemorySize, smem_bytes);

    const int n_windows = in_sizes[0] / (49 * 128);   // 4096
    wmsa_fused_kernel<<<n_windows, NTHR, smem_bytes>>>(x, qkv_b, proj_b, out);
}

// round 12
// speedup vs baseline: 1.8377x; 1.1800x over previous
#include <cuda_runtime.h>

#define SCALE 0.17677669529663687f
#define NTHR  256

// u32-word smem offsets — per-CTA smem = 97,792 B (2 CTAs/SM)
// XHH [0,3808)  : hi plane, 56 rows x 68 words (stride 272B, LDSM-clean)
// XHL [3808,7616): lo plane
// KH  [7616,15232): uint2 56x68 (hi,lo packed) — B operand for QK
// VT  [15232,24448): uint2 128x36 — B operand for AV
// AT overlay over XH planes: uint2, 4*49 rows x 36 = 7056 u2 = 14112 words < 15232
// OVH/OVL overlay over VT: 15232 / 19040, each 3808 words
#define SM_U2 12224

__device__ uint4  gW4[64 * 8 * 8 * 4];      // fragment-major pre-split weights
__device__ float2 gBM[64 * 4 * 7 * 49 * 4]; // bias+mask: [wm][h][jb][li][t]

__device__ __forceinline__ unsigned pack_bf(float x0, float x1) {
    unsigned r;
    asm("cvt.rn.bf16x2.f32 %0, %1, %2;" : "=r"(r) : "f"(x1), "f"(x0));
    return r;
}
__device__ __forceinline__ uint2 split_pack(float x0, float x1) {
    unsigned h = pack_bf(x0, x1);
    float h0 = __uint_as_float(h << 16);
    float h1 = __uint_as_float(h & 0xffff0000u);
    unsigned l = pack_bf(x0 - h0, x1 - h1);
    return make_uint2(h, l);
}
__device__ __forceinline__ void mmabf(float* d, const unsigned* a, const unsigned* b) {
    asm volatile("mma.sync.aligned.m16n8k16.row.col.f32.bf16.bf16.f32 "
        "{%0,%1,%2,%3},{%4,%5,%6,%7},{%8,%9},{%0,%1,%2,%3};"
        : "+f"(d[0]), "+f"(d[1]), "+f"(d[2]), "+f"(d[3])
        : "r"(a[0]), "r"(a[1]), "r"(a[2]), "r"(a[3]), "r"(b[0]), "r"(b[1]));
}
__device__ __forceinline__ void mma3(float* d, const unsigned ah[4], const unsigned al[4],
                                     uint2 b0, uint2 b1) {
    unsigned bh[2] = {b0.x, b1.x};
    unsigned bl[2] = {b0.y, b1.y};
    mmabf(d, ah, bl);
    mmabf(d, al, bh);
    mmabf(d, ah, bh);
}
__device__ __forceinline__ void ldsm4(unsigned r[4], unsigned a) {
    asm volatile("ldmatrix.sync.aligned.m8n8.x4.shared.b16 {%0,%1,%2,%3}, [%4];"
        : "=r"(r[0]), "=r"(r[1]), "=r"(r[2]), "=r"(r[3]) : "r"(a));
}

// Dense stage: warp computes 32 rows (two 16-row subtiles) x 32 cols, K=128.
// hb/lb = byte smem addresses of the hi/lo A planes, pre-offset by rbase row + lane.
__device__ __forceinline__ void mma_dense_ldsm(unsigned hb, unsigned lb,
                                               const uint4* __restrict__ gBw,
                                               float d[2][4][4], int lane)
{
    #pragma unroll
    for (int kb = 0; kb < 8; ++kb) {
        unsigned ah0[4], al0[4], ah1[4], al1[4];
        ldsm4(ah0, hb + kb * 32);
        ldsm4(al0, lb + kb * 32);
        ldsm4(ah1, hb + 4352 + kb * 32);     // +16 rows * 272B
        ldsm4(al1, lb + 4352 + kb * 32);
        #pragma unroll
        for (int nb = 0; nb < 4; ++nb) {
            uint4 f = gBw[nb * 256 + kb * 32 + lane];   // 512B coalesced
            uint2 b0 = make_uint2(f.x, f.y);
            uint2 b1 = make_uint2(f.z, f.w);
            mma3(d[0][nb], ah0, al0, b0, b1);
            mma3(d[1][nb], ah1, al1, b0, b1);
        }
    }
}

// combined prep: blocks [0,64) build gW4, blocks [64,..) build gBM
__global__ void prep_all(const float* __restrict__ qkv_w,
                         const float* __restrict__ proj_w,
                         const float* __restrict__ attn_mask,
                         const float* __restrict__ bias_table,
                         const int*   __restrict__ rel_idx)
{
    if (blockIdx.x < 64) {
        int idx = blockIdx.x * 256 + threadIdx.x;       // 0..16383
        int t    = idx & 3;
        int g    = (idx >> 2) & 7;
        int kb   = (idx >> 5) & 7;
        int cblk = idx >> 8;
        int col  = cblk * 8 + g;
        const float* src = (col < 384) ? (qkv_w + (size_t)col * 128)
                                       : (proj_w + (size_t)(col - 384) * 128);
        int w0 = kb * 8 + t, w1 = w0 + 4;
        uint2 p0 = split_pack(src[2 * w0], src[2 * w0 + 1]);
        uint2 p1 = split_pack(src[2 * w1], src[2 * w1 + 1]);
        gW4[idx] = make_uint4(p0.x, p0.y, p1.x, p1.y);
    } else {
        int idx = (blockIdx.x - 64) * 256 + threadIdx.x;
        if (idx >= 64 * 4 * 7 * 49 * 4) return;
        int t  = idx & 3;
        int q  = idx >> 2;
        int li = q % 49;   q /= 49;
        int jb = q % 7;    q /= 7;
        int h  = q & 3;
        int wm = q >> 2;
        int j0 = jb * 8 + 2 * t;
        float v0 = -1e30f, v1 = -1e30f;
        if (j0 < 49)
            v0 = bias_table[rel_idx[li * 49 + j0] * 4 + h] + attn_mask[wm * 2401 + li * 49 + j0];
        if (j0 + 1 < 49)
            v1 = bias_table[rel_idx[li * 49 + j0 + 1] * 4 + h] + attn_mask[wm * 2401 + li * 49 + j0 + 1];
        gBM[idx] = make_float2(v0, v1);
    }
}

__global__ __launch_bounds__(NTHR, 2)
void wmsa_fused_kernel(const float* __restrict__ x,
                       const float* __restrict__ qkv_b,
                       const float* __restrict__ proj_b,
                       float* __restrict__ out)
{
    extern __shared__ unsigned sm32[];
    unsigned* XHH = sm32;                    // hi plane (x, then q)
    unsigned* XHL = sm32 + 3808;             // lo plane
    uint2*    KH  = (uint2*)(sm32 + 7616);
    uint2*    VT  = (uint2*)(sm32 + 15232);
    uint2*    AT  = (uint2*)sm32;            // overlay over XH planes
    unsigned* OVH = sm32 + 15232;            // overlay over VT
    unsigned* OVL = sm32 + 19040;

    const int tid  = threadIdx.x;
    const int bx   = blockIdx.x;
    const int lane = tid & 31;
    const int wid  = tid >> 5;               // 0..7
    const int g    = lane >> 2;
    const int t    = lane & 3;

    const int mt2   = wid >> 2;              // 0..1
    const int nh    = wid & 3;
    const int rbase = mt2 * 32;
    const int cb    = nh * 32;
    const uint4* gBq = gW4 + (cb >> 3) * 256;

    const unsigned sb = (unsigned)__cvta_generic_to_shared(sm32);
    const unsigned rowoff = (lane & 15) * 272 + (lane >> 4) * 16;  // canonical LDSM addr
    const unsigned xhh_b = sb + rowoff;
    const unsigned xhl_b = sb + 3808u * 4 + rowoff;
    const unsigned ovh_b = sb + 15232u * 4 + rowoff;
    const unsigned ovl_b = sb + 19040u * 4 + rowoff;

    // ---------------- phase 0: load+split x (planes) ; zero VT + KH pads ----------------
    {
        const float2* xg = (const float2*)(x + (size_t)bx * 49 * 128);
        for (int idx = tid; idx < 49 * 64; idx += NTHR) {
            float2 v = xg[idx];
            uint2 p = split_pack(v.x, v.y);
            int o = (idx >> 6) * 68 + (idx & 63);
            XHH[o] = p.x;
            XHL[o] = p.y;
        }
        for (int idx = tid; idx < 128 * 36; idx += NTHR)
            VT[idx] = make_uint2(0, 0);
        for (int idx = tid; idx < 7 * 68; idx += NTHR)      // KH rows 49..55 = 0
            KH[49 * 68 + idx] = make_uint2(0, 0);
    }
    __syncthreads();

    // ---------------- phase 1: K, V, Q ----------------
    {   // K (col block 16)
        float d[2][4][4] = {};
        mma_dense_ldsm(xhh_b + rbase * 272, xhl_b + rbase * 272, gBq + 16 * 256, d, lane);
        #pragma unroll
        for (int sub = 0; sub < 2; ++sub) {
            int r0 = rbase + sub * 16 + g, r1 = r0 + 8;
            #pragma unroll
            for (int nb = 0; nb < 4; ++nb) {
                int c = cb + nb * 8 + 2 * t;
                float b0 = qkv_b[128 + c], b1 = qkv_b[129 + c];
                int wcol = c >> 1;
                if (r0 < 49) KH[r0 * 68 + wcol] = split_pack(d[sub][nb][0] + b0, d[sub][nb][1] + b1);
                if (r1 < 49) KH[r1 * 68 + wcol] = split_pack(d[sub][nb][2] + b0, d[sub][nb][3] + b1);
            }
        }
    }
    {   // V (col block 32) -> VT transposed via shfl pairing
        float d[2][4][4] = {};
        mma_dense_ldsm(xhh_b + rbase * 272, xhl_b + rbase * 272, gBq + 32 * 256, d, lane);
        #pragma unroll
        for (int sub = 0; sub < 2; ++sub) {
            #pragma unroll
            for (int nb = 0; nb < 4; ++nb) {
                int c = cb + nb * 8 + 2 * t;
                float b0 = qkv_b[256 + c], b1 = qkv_b[257 + c];
                #pragma unroll
                for (int rr = 0; rr < 2; ++rr) {
                    float vc  = d[sub][nb][2 * rr]     + b0;
                    float vc1 = d[sub][nb][2 * rr + 1] + b1;
                    float oc  = __shfl_xor_sync(0xffffffffu, vc, 4);
                    float oc1 = __shfl_xor_sync(0xffffffffu, vc1, 4);
                    int il = rbase + sub * 16 + rr * 8 + g;
                    if (!(g & 1) && il < 49) {
                        float e1 = (il + 1 < 49) ? oc  : 0.f;
                        float f1 = (il + 1 < 49) ? oc1 : 0.f;
                        int u = il >> 1;
                        VT[c * 36 + u]       = split_pack(vc,  e1);
                        VT[(c + 1) * 36 + u] = split_pack(vc1, f1);
                    }
                }
            }
        }
    }
    {   // Q (col block 0): compute, sync, overwrite XH planes
        float d[2][4][4] = {};
        mma_dense_ldsm(xhh_b + rbase * 272, xhl_b + rbase * 272, gBq, d, lane);
        __syncthreads();                      // all XH reads done
        #pragma unroll
        for (int sub = 0; sub < 2; ++sub) {
            int r0 = rbase + sub * 16 + g, r1 = r0 + 8;
            #pragma unroll
            for (int nb = 0; nb < 4; ++nb) {
                int c = cb + nb * 8 + 2 * t;
                float b0 = qkv_b[c], b1 = qkv_b[c + 1];
                int wcol = c >> 1;
                if (r0 < 49) {
                    uint2 p = split_pack((d[sub][nb][0] + b0) * SCALE, (d[sub][nb][1] + b1) * SCALE);
                    XHH[r0 * 68 + wcol] = p.x;
                    XHL[r0 * 68 + wcol] = p.y;
                }
                if (r1 < 49) {
                    uint2 p = split_pack((d[sub][nb][2] + b0) * SCALE, (d[sub][nb][3] + b1) * SCALE);
                    XHH[r1 * 68 + wcol] = p.x;
                    XHL[r1 * 68 + wcol] = p.y;
                }
            }
        }
    }
    __syncthreads();

    // ---------------- phase 2: QK^T into regs (2 tasks/warp, LDSM A) ----------------
    float d2[2][7][4];
    #pragma unroll
    for (int it = 0; it < 2; ++it) {
        int task = wid + 8 * it;
        int h = task >> 2, qt = task & 3;
        int row0 = qt * 16;
        #pragma unroll
        for (int jb = 0; jb < 7; ++jb)
            #pragma unroll
            for (int e = 0; e < 4; ++e) d2[it][jb][e] = 0.f;
        #pragma unroll
        for (int kb2 = 0; kb2 < 2; ++kb2) {
            int kb = 2 * h + kb2;
            unsigned ah[4], al[4];
            ldsm4(ah, xhh_b + row0 * 272 + kb * 32);
            ldsm4(al, xhl_b + row0 * 272 + kb * 32);
            int kw = kb * 8 + t;
            #pragma unroll
            for (int jb = 0; jb < 7; ++jb) {
                int kr = jb * 8 + g;
                mma3(d2[it][jb], ah, al, KH[kr * 68 + kw], KH[kr * 68 + kw + 4]);
            }
        }
    }
    __syncthreads();                          // XH/KH reads done; AT writable

    // ---------------- phase 3: folded bias+mask + softmax -> packed AT ----------------
    #pragma unroll
    for (int it = 0; it < 2; ++it) {
        int task = wid + 8 * it;
        int h = task >> 2, qt = task & 3;
        const float2* bmh = gBM + ((size_t)(bx & 63) * 4 + h) * (7 * 49 * 4);
        #pragma unroll
        for (int rr = 0; rr < 2; ++rr) {
            int li = qt * 16 + rr * 8 + g;
            bool okr = (li < 49);
            int lic = min(li, 48);
            float sv[14];
            float mx = -INFINITY;
            #pragma unroll
            for (int jb = 0; jb < 7; ++jb) {
                float2 bm = bmh[(jb * 49 + lic) * 4 + t];
                float v0 = d2[it][jb][rr * 2]     + bm.x;
                float v1 = d2[it][jb][rr * 2 + 1] + bm.y;
                sv[2 * jb]     = v0;
                sv[2 * jb + 1] = v1;
                mx = fmaxf(mx, fmaxf(v0, v1));
            }
            mx = fmaxf(mx, __shfl_xor_sync(0xffffffffu, mx, 1));
            mx = fmaxf(mx, __shfl_xor_sync(0xffffffffu, mx, 2));
            float sum = 0.f;
            #pragma unroll
            for (int n = 0; n < 14; ++n) { sv[n] = __expf(sv[n] - mx); sum += sv[n]; }
            sum += __shfl_xor_sync(0xffffffffu, sum, 1);
            sum += __shfl_xor_sync(0xffffffffu, sum, 2);
            float inv = 1.f / sum;
            if (okr) {
                uint2* arow = AT + ((size_t)h * 49 + li) * 36;
                #pragma unroll
                for (int jb = 0; jb < 7; ++jb)
                    arow[4 * jb + t] = split_pack(sv[2 * jb] * inv, sv[2 * jb + 1] * inv);
                arow[28 + t] = make_uint2(0, 0);
            }
        }
    }
    __syncthreads();

    // ---------------- phase 4: AV into regs, then OV planes over VT ----------------
    float d4[2][4][4] = {};
    #pragma unroll
    for (int it = 0; it < 2; ++it) {
        int task = wid + 8 * it;
        int h = task >> 2, qt = task & 3;
        const uint2* ab = AT + (size_t)h * 49 * 36;
        int qa0 = min(qt * 16 + g, 48);
        int qa1 = min(qt * 16 + 8 + g, 48);
        #pragma unroll
        for (int kb = 0; kb < 4; ++kb) {
            int kw = kb * 8 + t;
            uint2 a0 = ab[qa0 * 36 + kw];
            uint2 a1 = ab[qa1 * 36 + kw];
            uint2 a2 = ab[qa0 * 36 + kw + 4];
            uint2 a3 = ab[qa1 * 36 + kw + 4];
            unsigned ah[4] = {a0.x, a1.x, a2.x, a3.x};
            unsigned al[4] = {a0.y, a1.y, a2.y, a3.y};
            #pragma unroll
            for (int nb = 0; nb < 4; ++nb) {
                int c = 32 * h + nb * 8 + g;
                mma3(d4[it][nb], ah, al, VT[c * 36 + kw], VT[c * 36 + kw + 4]);
            }
        }
    }
    __syncthreads();                          // VT reads done; OV planes writable
    #pragma unroll
    for (int it = 0; it < 2; ++it) {
        int task = wid + 8 * it;
        int h = task >> 2, qt = task & 3;
        int l0 = qt * 16 + g;
        #pragma unroll
        for (int nb = 0; nb < 4; ++nb) {
            int cw = 16 * h + nb * 4 + t;
            if (l0 < 49) {
                uint2 p = split_pack(d4[it][nb][0], d4[it][nb][1]);
                OVH[l0 * 68 + cw] = p.x;
                OVL[l0 * 68 + cw] = p.y;
            }
            if (l0 + 8 < 49) {
                uint2 p = split_pack(d4[it][nb][2], d4[it][nb][3]);
                OVH[(l0 + 8) * 68 + cw] = p.x;
                OVL[(l0 + 8) * 68 + cw] = p.y;
            }
        }
    }
    __syncthreads();

    // ---------------- phase 5: proj GEMM (col block 48) ----------------
    {
        float d[2][4][4] = {};
        mma_dense_ldsm(ovh_b + rbase * 272, ovl_b + rbase * 272, gBq + 48 * 256, d, lane);
        float* og = out + (size_t)bx * 49 * 128;
        #pragma unroll
        for (int sub = 0; sub < 2; ++sub) {
            int r0 = rbase + sub * 16 + g, r1 = r0 + 8;
            #pragma unroll
            for (int nb = 0; nb < 4; ++nb) {
                int c = cb + nb * 8 + 2 * t;
                float b0 = proj_b[c], b1 = proj_b[c + 1];
                if (r0 < 49)
                    *(float2*)(og + r0 * 128 + c) = make_float2(d[sub][nb][0] + b0, d[sub][nb][1] + b1);
                if (r1 < 49)
                    *(float2*)(og + r1 * 128 + c) = make_float2(d[sub][nb][2] + b0, d[sub][nb][3] + b1);
            }
        }
    }
}

extern "C" void kernel_launch(void* const* d_in, const int* in_sizes, int n_in,
                              void* d_out, int out_size)
{
    const float* x          = (const float*)d_in[0];
    const float* attn_mask  = (const float*)d_in[1];
    const float* qkv_w      = (const float*)d_in[2];
    const float* qkv_b      = (const float*)d_in[3];
    const float* proj_w     = (const float*)d_in[4];
    const float* proj_b     = (const float*)d_in[5];
    const float* bias_table = (const float*)d_in[6];
    const int*   rel_idx    = (const int*)d_in[7];
    float* out = (float*)d_out;

    const int bm_blocks = (64 * 4 * 7 * 49 * 4 + 255) / 256;   // 215
    prep_all<<<64 + bm_blocks, 256>>>(qkv_w, proj_w, attn_mask, bias_table, rel_idx);

    const int smem_bytes = SM_U2 * 8;                          // 97,792 B -> 2 CTAs/SM
    cudaFuncSetAttribute(wmsa_fused_kernel,
                         cudaFuncAttributeMaxDynamicSharedMemorySize, smem_bytes);

    const int n_windows = in_sizes[0] / (49 * 128);            // 4096
    wmsa_fused_kernel<<<n_windows, NTHR, smem_bytes>>>(x, qkv_b, proj_b, out);
}

// round 13
// speedup vs baseline: 1.9237x; 1.0468x over previous
#include <cuda_runtime.h>

#define SCALE 0.17677669529663687f
#define NTHR  256

// u32-word smem offsets — per-CTA smem = 97,792 B (2 CTAs/SM)
// XHH [0,3808)   : hi plane, 56 rows x 68 words (stride 272B, LDSM-clean)
// XHL [3808,7616): lo plane
// KH  [7616,15232): uint2 56x68 (hi,lo packed) — B operand for QK
// VT  [15232,24448): uint2 128x36 — B operand for AV
// OVH/OVL overlay over VT: 15232 / 19040, each 3808 words
#define SM_U2 12224

__device__ uint4  gW4[64 * 8 * 8 * 4];      // fragment-major pre-split weights
__device__ float2 gBM[64 * 4 * 7 * 49 * 4]; // bias+mask: [wm][h][jb][li][t]

__device__ __forceinline__ unsigned pack_bf(float x0, float x1) {
    unsigned r;
    asm("cvt.rn.bf16x2.f32 %0, %1, %2;" : "=r"(r) : "f"(x1), "f"(x0));
    return r;
}
__device__ __forceinline__ uint2 split_pack(float x0, float x1) {
    unsigned h = pack_bf(x0, x1);
    float h0 = __uint_as_float(h << 16);
    float h1 = __uint_as_float(h & 0xffff0000u);
    unsigned l = pack_bf(x0 - h0, x1 - h1);
    return make_uint2(h, l);
}
__device__ __forceinline__ void mmabf(float* d, const unsigned* a, const unsigned* b) {
    asm volatile("mma.sync.aligned.m16n8k16.row.col.f32.bf16.bf16.f32 "
        "{%0,%1,%2,%3},{%4,%5,%6,%7},{%8,%9},{%0,%1,%2,%3};"
        : "+f"(d[0]), "+f"(d[1]), "+f"(d[2]), "+f"(d[3])
        : "r"(a[0]), "r"(a[1]), "r"(a[2]), "r"(a[3]), "r"(b[0]), "r"(b[1]));
}
__device__ __forceinline__ void mma3(float* d, const unsigned ah[4], const unsigned al[4],
                                     uint2 b0, uint2 b1) {
    unsigned bh[2] = {b0.x, b1.x};
    unsigned bl[2] = {b0.y, b1.y};
    mmabf(d, ah, bl);
    mmabf(d, al, bh);
    mmabf(d, ah, bh);
}
__device__ __forceinline__ void ldsm4(unsigned r[4], unsigned a) {
    asm volatile("ldmatrix.sync.aligned.m8n8.x4.shared.b16 {%0,%1,%2,%3}, [%4];"
        : "=r"(r[0]), "=r"(r[1]), "=r"(r[2]), "=r"(r[3]) : "r"(a));
}

// Dense stage: warp computes 32 rows (two 16-row subtiles) x 32 cols, K=128.
__device__ __forceinline__ void mma_dense_ldsm(unsigned hb, unsigned lb,
                                               const uint4* __restrict__ gBw,
                                               float d[2][4][4], int lane)
{
    #pragma unroll
    for (int kb = 0; kb < 8; ++kb) {
        unsigned ah0[4], al0[4], ah1[4], al1[4];
        ldsm4(ah0, hb + kb * 32);
        ldsm4(al0, lb + kb * 32);
        ldsm4(ah1, hb + 4352 + kb * 32);     // +16 rows * 272B
        ldsm4(al1, lb + 4352 + kb * 32);
        #pragma unroll
        for (int nb = 0; nb < 4; ++nb) {
            uint4 f = gBw[nb * 256 + kb * 32 + lane];   // 512B coalesced
            uint2 b0 = make_uint2(f.x, f.y);
            uint2 b1 = make_uint2(f.z, f.w);
            mma3(d[0][nb], ah0, al0, b0, b1);
            mma3(d[1][nb], ah1, al1, b0, b1);
        }
    }
}

// combined prep: blocks [0,64) build gW4, blocks [64,..) build gBM
__global__ void prep_all(const float* __restrict__ qkv_w,
                         const float* __restrict__ proj_w,
                         const float* __restrict__ attn_mask,
                         const float* __restrict__ bias_table,
                         const int*   __restrict__ rel_idx)
{
    if (blockIdx.x < 64) {
        int idx = blockIdx.x * 256 + threadIdx.x;       // 0..16383
        int t    = idx & 3;
        int g    = (idx >> 2) & 7;
        int kb   = (idx >> 5) & 7;
        int cblk = idx >> 8;
        int col  = cblk * 8 + g;
        const float* src = (col < 384) ? (qkv_w + (size_t)col * 128)
                                       : (proj_w + (size_t)(col - 384) * 128);
        int w0 = kb * 8 + t, w1 = w0 + 4;
        uint2 p0 = split_pack(src[2 * w0], src[2 * w0 + 1]);
        uint2 p1 = split_pack(src[2 * w1], src[2 * w1 + 1]);
        gW4[idx] = make_uint4(p0.x, p0.y, p1.x, p1.y);
    } else {
        int idx = (blockIdx.x - 64) * 256 + threadIdx.x;
        if (idx >= 64 * 4 * 7 * 49 * 4) return;
        int t  = idx & 3;
        int q  = idx >> 2;
        int li = q % 49;   q /= 49;
        int jb = q % 7;    q /= 7;
        int h  = q & 3;
        int wm = q >> 2;
        int j0 = jb * 8 + 2 * t;
        float v0 = -1e30f, v1 = -1e30f;
        if (j0 < 49)
            v0 = bias_table[rel_idx[li * 49 + j0] * 4 + h] + attn_mask[wm * 2401 + li * 49 + j0];
        if (j0 + 1 < 49)
            v1 = bias_table[rel_idx[li * 49 + j0 + 1] * 4 + h] + attn_mask[wm * 2401 + li * 49 + j0 + 1];
        gBM[idx] = make_float2(v0, v1);
    }
}

__global__ __launch_bounds__(NTHR, 2)
void wmsa_fused_kernel(const float* __restrict__ x,
                       const float* __restrict__ qkv_b,
                       const float* __restrict__ proj_b,
                       float* __restrict__ out)
{
    extern __shared__ unsigned sm32[];
    unsigned* XHH = sm32;                    // hi plane (x, then q)
    unsigned* XHL = sm32 + 3808;             // lo plane
    uint2*    KH  = (uint2*)(sm32 + 7616);
    uint2*    VT  = (uint2*)(sm32 + 15232);
    unsigned* OVH = sm32 + 15232;            // overlay over VT
    unsigned* OVL = sm32 + 19040;

    const int tid  = threadIdx.x;
    const int bx   = blockIdx.x;
    const int lane = tid & 31;
    const int wid  = tid >> 5;               // 0..7
    const int g    = lane >> 2;
    const int t    = lane & 3;

    const int mt2   = wid >> 2;              // 0..1
    const int nh    = wid & 3;
    const int rbase = mt2 * 32;
    const int cb    = nh * 32;
    const uint4* gBq = gW4 + (cb >> 3) * 256;

    const unsigned sb = (unsigned)__cvta_generic_to_shared(sm32);
    const unsigned rowoff = (lane & 15) * 272 + (lane >> 4) * 16;  // canonical LDSM addr
    const unsigned xhh_b = sb + rowoff;
    const unsigned xhl_b = sb + 3808u * 4 + rowoff;
    const unsigned ovh_b = sb + 15232u * 4 + rowoff;
    const unsigned ovl_b = sb + 19040u * 4 + rowoff;

    // ---------------- phase 0: load+split x (planes) ; zero VT + KH pads ----------------
    {
        const float2* xg = (const float2*)(x + (size_t)bx * 49 * 128);
        for (int idx = tid; idx < 49 * 64; idx += NTHR) {
            float2 v = xg[idx];
            uint2 p = split_pack(v.x, v.y);
            int o = (idx >> 6) * 68 + (idx & 63);
            XHH[o] = p.x;
            XHL[o] = p.y;
        }
        for (int idx = tid; idx < 128 * 36; idx += NTHR)
            VT[idx] = make_uint2(0, 0);
        for (int idx = tid; idx < 7 * 68; idx += NTHR)      // KH rows 49..55 = 0
            KH[49 * 68 + idx] = make_uint2(0, 0);
    }
    __syncthreads();

    // ---------------- phase 1: K, V, Q ----------------
    {   // K (col block 16)
        float d[2][4][4] = {};
        mma_dense_ldsm(xhh_b + rbase * 272, xhl_b + rbase * 272, gBq + 16 * 256, d, lane);
        #pragma unroll
        for (int sub = 0; sub < 2; ++sub) {
            int r0 = rbase + sub * 16 + g, r1 = r0 + 8;
            #pragma unroll
            for (int nb = 0; nb < 4; ++nb) {
                int c = cb + nb * 8 + 2 * t;
                float b0 = qkv_b[128 + c], b1 = qkv_b[129 + c];
                int wcol = c >> 1;
                if (r0 < 49) KH[r0 * 68 + wcol] = split_pack(d[sub][nb][0] + b0, d[sub][nb][1] + b1);
                if (r1 < 49) KH[r1 * 68 + wcol] = split_pack(d[sub][nb][2] + b0, d[sub][nb][3] + b1);
            }
        }
    }
    {   // V (col block 32) -> VT transposed via shfl pairing
        float d[2][4][4] = {};
        mma_dense_ldsm(xhh_b + rbase * 272, xhl_b + rbase * 272, gBq + 32 * 256, d, lane);
        #pragma unroll
        for (int sub = 0; sub < 2; ++sub) {
            #pragma unroll
            for (int nb = 0; nb < 4; ++nb) {
                int c = cb + nb * 8 + 2 * t;
                float b0 = qkv_b[256 + c], b1 = qkv_b[257 + c];
                #pragma unroll
                for (int rr = 0; rr < 2; ++rr) {
                    float vc  = d[sub][nb][2 * rr]     + b0;
                    float vc1 = d[sub][nb][2 * rr + 1] + b1;
                    float oc  = __shfl_xor_sync(0xffffffffu, vc, 4);
                    float oc1 = __shfl_xor_sync(0xffffffffu, vc1, 4);
                    int il = rbase + sub * 16 + rr * 8 + g;
                    if (!(g & 1) && il < 49) {
                        float e1 = (il + 1 < 49) ? oc  : 0.f;
                        float f1 = (il + 1 < 49) ? oc1 : 0.f;
                        int u = il >> 1;
                        VT[c * 36 + u]       = split_pack(vc,  e1);
                        VT[(c + 1) * 36 + u] = split_pack(vc1, f1);
                    }
                }
            }
        }
    }
    {   // Q (col block 0): compute, sync, overwrite XH planes
        float d[2][4][4] = {};
        mma_dense_ldsm(xhh_b + rbase * 272, xhl_b + rbase * 272, gBq, d, lane);
        __syncthreads();                      // all XH reads done
        #pragma unroll
        for (int sub = 0; sub < 2; ++sub) {
            int r0 = rbase + sub * 16 + g, r1 = r0 + 8;
            #pragma unroll
            for (int nb = 0; nb < 4; ++nb) {
                int c = cb + nb * 8 + 2 * t;
                float b0 = qkv_b[c], b1 = qkv_b[c + 1];
                int wcol = c >> 1;
                if (r0 < 49) {
                    uint2 p = split_pack((d[sub][nb][0] + b0) * SCALE, (d[sub][nb][1] + b1) * SCALE);
                    XHH[r0 * 68 + wcol] = p.x;
                    XHL[r0 * 68 + wcol] = p.y;
                }
                if (r1 < 49) {
                    uint2 p = split_pack((d[sub][nb][2] + b0) * SCALE, (d[sub][nb][3] + b1) * SCALE);
                    XHH[r1 * 68 + wcol] = p.x;
                    XHL[r1 * 68 + wcol] = p.y;
                }
            }
        }
    }
    __syncthreads();

    // ---------------- phases 2-4 fused: per-task QK -> softmax -> AV, all in regs ----------------
    float d4[2][4][4] = {};
    #pragma unroll
    for (int it = 0; it < 2; ++it) {
        int task = wid + 8 * it;              // 0..15
        int h = task >> 2, qt = task & 3;
        int row0 = qt * 16;

        // --- QK^T (A = q rows via LDSM, B = KH) ---
        float dq[7][4];
        #pragma unroll
        for (int jb = 0; jb < 7; ++jb)
            #pragma unroll
            for (int e = 0; e < 4; ++e) dq[jb][e] = 0.f;
        #pragma unroll
        for (int kb2 = 0; kb2 < 2; ++kb2) {
            int kb = 2 * h + kb2;
            unsigned ah[4], al[4];
            ldsm4(ah, xhh_b + row0 * 272 + kb * 32);
            ldsm4(al, xhl_b + row0 * 272 + kb * 32);
            int kw = kb * 8 + t;
            #pragma unroll
            for (int jb = 0; jb < 7; ++jb) {
                int kr = jb * 8 + g;
                mma3(dq[jb], ah, al, KH[kr * 68 + kw], KH[kr * 68 + kw + 4]);
            }
        }

        // --- bias+mask + softmax -> packed A fragments (regs, no smem) ---
        uint2 pa[7], pb[7];                   // rows g / g+8, per jb: (hi,lo) of col pair
        const float2* bmh = gBM + ((size_t)(bx & 63) * 4 + h) * (7 * 49 * 4);
        #pragma unroll
        for (int rr = 0; rr < 2; ++rr) {
            int li = row0 + rr * 8 + g;
            int lic = min(li, 48);
            float sv[14];
            float mx = -INFINITY;
            #pragma unroll
            for (int jb = 0; jb < 7; ++jb) {
                float2 bm = bmh[(jb * 49 + lic) * 4 + t];
                float v0 = dq[jb][rr * 2]     + bm.x;
                float v1 = dq[jb][rr * 2 + 1] + bm.y;
                sv[2 * jb]     = v0;
                sv[2 * jb + 1] = v1;
                mx = fmaxf(mx, fmaxf(v0, v1));
            }
            mx = fmaxf(mx, __shfl_xor_sync(0xffffffffu, mx, 1));
            mx = fmaxf(mx, __shfl_xor_sync(0xffffffffu, mx, 2));
            float sum = 0.f;
            #pragma unroll
            for (int n = 0; n < 14; ++n) { sv[n] = __expf(sv[n] - mx); sum += sv[n]; }
            sum += __shfl_xor_sync(0xffffffffu, sum, 1);
            sum += __shfl_xor_sync(0xffffffffu, sum, 2);
            float inv = 1.f / sum;
            uint2* dst = rr ? pb : pa;
            #pragma unroll
            for (int jb = 0; jb < 7; ++jb)
                dst[jb] = split_pack(sv[2 * jb] * inv, sv[2 * jb + 1] * inv);
        }

        // --- AV (A = packed probs from regs, B = VT) ---
        #pragma unroll
        for (int kb = 0; kb < 4; ++kb) {
            const int jb0 = 2 * kb, jb1 = 2 * kb + 1;
            unsigned ah[4], al[4];
            ah[0] = pa[jb0].x;  al[0] = pa[jb0].y;
            ah[1] = pb[jb0].x;  al[1] = pb[jb0].y;
            if (jb1 < 7) {
                ah[2] = pa[jb1].x;  al[2] = pa[jb1].y;
                ah[3] = pb[jb1].x;  al[3] = pb[jb1].y;
            } else {
                ah[2] = 0; al[2] = 0; ah[3] = 0; al[3] = 0;
            }
            int kw = kb * 8 + t;
            #pragma unroll
            for (int nb = 0; nb < 4; ++nb) {
                int c = 32 * h + nb * 8 + g;
                mma3(d4[it][nb], ah, al, VT[c * 36 + kw], VT[c * 36 + kw + 4]);
            }
        }
    }
    __syncthreads();                          // VT reads done; OV planes writable

    #pragma unroll
    for (int it = 0; it < 2; ++it) {
        int task = wid + 8 * it;
        int h = task >> 2, qt = task & 3;
        int l0 = qt * 16 + g;
        #pragma unroll
        for (int nb = 0; nb < 4; ++nb) {
            int cw = 16 * h + nb * 4 + t;
            if (l0 < 49) {
                uint2 p = split_pack(d4[it][nb][0], d4[it][nb][1]);
                OVH[l0 * 68 + cw] = p.x;
                OVL[l0 * 68 + cw] = p.y;
            }
            if (l0 + 8 < 49) {
                uint2 p = split_pack(d4[it][nb][2], d4[it][nb][3]);
                OVH[(l0 + 8) * 68 + cw] = p.x;
                OVL[(l0 + 8) * 68 + cw] = p.y;
            }
        }
    }
    __syncthreads();

    // ---------------- phase 5: proj GEMM (col block 48) ----------------
    {
        float d[2][4][4] = {};
        mma_dense_ldsm(ovh_b + rbase * 272, ovl_b + rbase * 272, gBq + 48 * 256, d, lane);
        float* og = out + (size_t)bx * 49 * 128;
        #pragma unroll
        for (int sub = 0; sub < 2; ++sub) {
            int r0 = rbase + sub * 16 + g, r1 = r0 + 8;
            #pragma unroll
            for (int nb = 0; nb < 4; ++nb) {
                int c = cb + nb * 8 + 2 * t;
                float b0 = proj_b[c], b1 = proj_b[c + 1];
                if (r0 < 49)
                    *(float2*)(og + r0 * 128 + c) = make_float2(d[sub][nb][0] + b0, d[sub][nb][1] + b1);
                if (r1 < 49)
                    *(float2*)(og + r1 * 128 + c) = make_float2(d[sub][nb][2] + b0, d[sub][nb][3] + b1);
            }
        }
    }
}

extern "C" void kernel_launch(void* const* d_in, const int* in_sizes, int n_in,
                              void* d_out, int out_size)
{
    const float* x          = (const float*)d_in[0];
    const float* attn_mask  = (const float*)d_in[1];
    const float* qkv_w      = (const float*)d_in[2];
    const float* qkv_b      = (const float*)d_in[3];
    const float* proj_w     = (const float*)d_in[4];
    const float* proj_b     = (const float*)d_in[5];
    const float* bias_table = (const float*)d_in[6];
    const int*   rel_idx    = (const int*)d_in[7];
    float* out = (float*)d_out;

    const int bm_blocks = (64 * 4 * 7 * 49 * 4 + 255) / 256;   // 215
    prep_all<<<64 + bm_blocks, 256>>>(qkv_w, proj_w, attn_mask, bias_table, rel_idx);

    const int smem_bytes = SM_U2 * 8;                          // 97,792 B -> 2 CTAs/SM
    cudaFuncSetAttribute(wmsa_fused_kernel,
                         cudaFuncAttributeMaxDynamicSharedMemorySize, smem_bytes);

    const int n_windows = in_sizes[0] / (49 * 128);            // 4096
    wmsa_fused_kernel<<<n_windows, NTHR, smem_bytes>>>(x, qkv_b, proj_b, out);
}